// round 13
// baseline (speedup 1.0000x reference)
#include <cuda_runtime.h>
#include <cuda_fp16.h>
#include <math.h>
#include <stdint.h>

#define Bn 32768
#define Tn 16
#define BH (Bn * 128)

// ---------------- device scratch ----------------
__device__ __align__(16) __half g_feath[BH];
__device__ __align__(16) __half g_h1h[2 * BH];
__device__ __align__(16) __half g_h2h[2 * BH];
__device__ float    g_c1t[BH];   // transposed: [col][row]
__device__ float    g_c2t[BH];
__device__ __align__(16) uint32_t g_W1h[12 * 8192];
__device__ __align__(16) uint32_t g_W2h[8 * 8192];
__device__ __align__(16) uint32_t g_W2c[7168];
__device__ __align__(16) uint32_t g_W3c[32768];
__device__ float    g_b1p[512];   // gate-interleaved n' = 4j+gate
__device__ float    g_b2p[512];

// ---------------- helpers ----------------
__device__ __forceinline__ uint32_t smem_u32(const void* p) {
    uint32_t r;
    asm("{ .reg .u64 t; cvta.to.shared.u64 t, %1; cvt.u32.u64 %0, t; }" : "=r"(r) : "l"(p));
    return r;
}
#define CP16(dst, src) asm volatile("cp.async.cg.shared.global [%0], [%1], 16;" :: "r"(dst), "l"(src))
#define CP_COMMIT()    asm volatile("cp.async.commit_group;" ::: "memory")
#define CP_WAIT0()     asm volatile("cp.async.wait_group 0;" ::: "memory")
#define CP_WAIT1()     asm volatile("cp.async.wait_group 1;" ::: "memory")

#define MMA_F16(d, a, b0v, b1v) \
    asm volatile("mma.sync.aligned.m16n8k16.row.col.f32.f16.f16.f32 " \
        "{%0,%1,%2,%3}, {%4,%5,%6,%7}, {%8,%9}, {%0,%1,%2,%3};" \
        : "+f"((d)[0]), "+f"((d)[1]), "+f"((d)[2]), "+f"((d)[3]) \
        : "r"((a)[0]), "r"((a)[1]), "r"((a)[2]), "r"((a)[3]), "r"(b0v), "r"(b1v))

__device__ __forceinline__ uint32_t pack_h2(float lo, float hi) {
    __half2 h = __floats2half2_rn(lo, hi);
    uint32_t u;
    memcpy(&u, &h, 4);
    return u;
}
__device__ __forceinline__ float sigf(float x) { return __fdividef(1.0f, 1.0f + __expf(-x)); }
__device__ __forceinline__ float tanhx(float x) { return __fdividef(2.0f, 1.0f + __expf(-2.0f * x)) - 1.0f; }
__device__ __forceinline__ float eluf(float x) { return x > 0.0f ? x : expm1f(x); }

// ---------------- weight prep (same fragment orders as R12) ----------------
__global__ void prep_kernel(const float* __restrict__ w_ih1, const float* __restrict__ w_hh1,
                            const float* __restrict__ b_ih1, const float* __restrict__ b_hh1,
                            const float* __restrict__ w_ih2, const float* __restrict__ w_hh2,
                            const float* __restrict__ b_ih2, const float* __restrict__ b_hh2,
                            const float* __restrict__ w2c, const float* __restrict__ w3c) {
    int i = blockIdx.x * blockDim.x + threadIdx.x;
    const int total1 = 12 * 8192;
    const int total2 = 8 * 8192;
    const int base3  = total1 + total2 + 1024;
    if (i < total1 + total2) {
        int li = (i < total1) ? i : i - total1;
        int w    = li & 3;
        int lane = (li >> 2) & 31;
        int jp   = (li >> 7) & 3;
        int s    = (li >> 9) & 1;
        int wn2  = (li >> 10) & 3;
        int half = (li >> 12) & 1;
        int ch   = li >> 13;
        int g = lane >> 2, t4 = lane & 3;
        int j8 = jp * 2 + (w >> 1);
        int k  = ch * 32 + s * 16 + 8 * (w & 1) + 2 * t4;
        int np = half * 256 + wn2 * 64 + j8 * 8 + g;
        int j = np >> 2, gate = np & 3;
        int n = gate * 128 + j;
        float f0, f1;
        if (i < total1) {
            if (k < 256) { f0 = w_ih1[n * 256 + k];        f1 = w_ih1[n * 256 + k + 1]; }
            else         { f0 = w_hh1[n * 128 + k - 256];  f1 = w_hh1[n * 128 + k - 255]; }
            g_W1h[li] = pack_h2(f0, f1);
        } else {
            if (k < 128) { f0 = w_ih2[n * 128 + k];        f1 = w_ih2[n * 128 + k + 1]; }
            else         { f0 = w_hh2[n * 128 + k - 128];  f1 = w_hh2[n * 128 + k - 127]; }
            g_W2h[li] = pack_h2(f0, f1);
        }
    } else if (i < total1 + total2 + 512) {
        int np = i - total1 - total2;
        int j = np >> 2, gate = np & 3;
        int n = gate * 128 + j;
        g_b1p[np] = b_ih1[n] + b_hh1[n];
    } else if (i < base3) {
        int np = i - total1 - total2 - 512;
        int j = np >> 2, gate = np & 3;
        int n = gate * 128 + j;
        g_b2p[np] = b_ih2[n] + b_hh2[n];
    } else if (i < base3 + 7168) {
        int wi = i - base3;
        int w01  = wi & 1;
        int lane = (wi >> 1) & 31;
        int j8   = (wi >> 6) & 7;
        int sc   = wi >> 9;
        int g = lane >> 2, t4 = lane & 3;
        int n = j8 * 8 + g;
        int k0 = sc * 16 + 2 * t4 + 8 * w01;
        g_W2c[wi] = pack_h2(w2c[n * 224 + k0], w2c[n * 224 + k0 + 1]);
    } else if (i < base3 + 7168 + 32768) {
        int wi = i - base3 - 7168;
        int w01  = wi & 1;
        int lane = (wi >> 1) & 31;
        int j8   = (wi >> 6) & 15;
        int sc   = wi >> 10;
        int g = lane >> 2, t4 = lane & 3;
        int n = j8 * 8 + g;
        int k0 = sc * 16 + 2 * t4 + 8 * w01;
        float f0, f1;
        {
            int ci2 = k0 >> 3, p = k0 & 7;
            f0 = (p < 7) ? w3c[n * 448 + ci2 * 7 + p] : 0.0f;
        }
        {
            int k1 = k0 + 1;
            int ci2 = k1 >> 3, p = k1 & 7;
            f1 = (p < 7) ? w3c[n * 448 + ci2 * 7 + p] : 0.0f;
        }
        g_W3c[wi] = pack_h2(f0, f1);
    }
}

// ---------------- conv stack (unchanged except fp16 feat output) ----------------
#define CXS   0
#define CW2F  640
#define CB2S  7808
#define CB3S  7872
#define CA3W  8000
#define CW3R  16192
#define CY1H  20288
#define CA2W  26944
#define CW1S  55616
#define CB1S  55840
#define CONV_SMEM_WORDS 55872
#define CONV_SMEM_BYTES (CONV_SMEM_WORDS * 4)

__global__ __launch_bounds__(256, 1)
void conv_kernel(const float* __restrict__ x,
                 const float* __restrict__ w1, const float* __restrict__ b1,
                 const float* __restrict__ b2, const float* __restrict__ b3) {
    extern __shared__ float sm[];
    __half* smh = (__half*)sm;
    uint32_t* smw = (uint32_t*)sm;
    uint32_t smb = smem_u32(sm);

    const int t    = threadIdx.x;
    const int lane = t & 31;
    const int wid  = t >> 5;
    const int g    = lane >> 2;
    const int t4   = lane & 3;
    const int b0g  = blockIdx.x * 32;

#pragma unroll
    for (int it = 0; it < 7; it++) {
        int gi = it * 1024 + t * 4;
        CP16(smb + (CW2F + gi) * 4, g_W2c + gi);
    }
    CP_COMMIT();

    for (int idx = t; idx < 608; idx += 256) {
        int b = idx / 19, q = idx - b * 19;
        sm[CXS + b * 20 + q] = x[(size_t)(b0g + b) * 19 + q];
    }
    if (t < 224) sm[CW1S + t] = w1[t];
    if (t < 32)  sm[CB1S + t] = b1[t];
    if (t < 64)  sm[CB2S + t] = b2[t];
    if (t < 128) sm[CB3S + t] = b3[t];
    __syncthreads();

    for (int idx = t; idx < 13312; idx += 256) {
        int b = idx / 416;
        int rem = idx - b * 416;
        int ci = rem / 13, q = rem - ci * 13;
        float s = sm[CB1S + ci];
#pragma unroll
        for (int k = 0; k < 7; k++) s += sm[CXS + b * 20 + q + k] * sm[CW1S + ci * 7 + k];
        smh[CY1H * 2 + idx] = __float2half(eluf(s));
    }
    for (int idx = t; idx < 8192; idx += 256) sm[CA3W + idx] = 0.0f;
    __syncthreads();

    {
        const int r = t;
        const int b = r >> 3, p = r & 7;
        const int xr = 2 * (r & 7);
        if (p < 7) {
            const __half* y1r = smh + CY1H * 2 + b * 416 + p;
            int c = 0;
            for (int ci = 0; ci < 32; ci++) {
                const __half* yq = y1r + ci * 13;
#pragma unroll
                for (int k = 0; k < 7; k++, c++) {
                    int ch = c >> 5, hc = c & 31;
                    int phys = (hc >> 1) ^ xr;
                    smh[(CA2W + ch * 4096 + r * 16 + phys) * 2 + (hc & 1)] = yq[k];
                }
            }
        } else {
            const __half z = __float2half(0.0f);
            for (int c = 0; c < 224; c++) {
                int ch = c >> 5, hc = c & 31;
                int phys = (hc >> 1) ^ xr;
                smh[(CA2W + ch * 4096 + r * 16 + phys) * 2 + (hc & 1)] = z;
            }
        }
    }
    CP_WAIT0();
    __syncthreads();

    auto issueW3 = [&](int i) {
        const uint32_t* src = g_W3c + i * 2048;
        uint32_t dst = smb + (CW3R + (i & 1) * 2048) * 4;
#pragma unroll
        for (int it = 0; it < 2; it++) {
            int gi = it * 1024 + t * 4;
            CP16(dst + gi * 4, src + gi);
        }
        CP_COMMIT();
    };
    issueW3(0);
    issueW3(1);

    const int wm2 = wid & 3;
    const int wn  = wid >> 2;
    float acc2[4][4][4];
#pragma unroll
    for (int mt = 0; mt < 4; mt++)
#pragma unroll
        for (int jp = 0; jp < 4; jp++)
#pragma unroll
            for (int q = 0; q < 4; q++) acc2[mt][jp][q] = 0.0f;

    for (int ch = 0; ch < 7; ch++) {
        const uint32_t* Ab = smw + CA2W + ch * 4096;
#pragma unroll
        for (int s = 0; s < 2; s++) {
            uint2 bf[4];
#pragma unroll
            for (int jp = 0; jp < 4; jp++) {
                int j8 = wn * 4 + jp;
                bf[jp] = *(const uint2*)(smw + CW2F + ((ch * 2 + s) * 8 + j8) * 64 + lane * 2);
            }
            int w0  = (s * 8 + t4) ^ (2 * g);
            int w1i = (s * 8 + 4 + t4) ^ (2 * g);
#pragma unroll
            for (int mt = 0; mt < 4; mt++) {
                int r0 = wm2 * 64 + mt * 16;
                uint32_t a[4];
                a[0] = Ab[(r0 + g) * 16 + w0];
                a[1] = Ab[(r0 + g + 8) * 16 + w0];
                a[2] = Ab[(r0 + g) * 16 + w1i];
                a[3] = Ab[(r0 + g + 8) * 16 + w1i];
#pragma unroll
                for (int jp = 0; jp < 4; jp++)
                    MMA_F16(acc2[mt][jp], a, bf[jp].x, bf[jp].y);
            }
        }
    }

#pragma unroll
    for (int mt = 0; mt < 4; mt++) {
#pragma unroll
        for (int q = 0; q < 4; q++) {
            int r = wm2 * 64 + mt * 16 + g + ((q >> 1) << 3);
            int p = r & 7;
            if (p == 7) continue;
            int b = r >> 3;
            int xr = 2 * (b & 7);
#pragma unroll
            for (int jp = 0; jp < 4; jp++) {
                int n = wn * 32 + jp * 8 + 2 * t4 + (q & 1);
                float v = eluf(acc2[mt][jp][q] + sm[CB2S + n]);
                int c3 = n * 8 + p;
                int ch3 = c3 >> 5, hc = c3 & 31;
                int phys = (hc >> 1) ^ xr;
                smh[(CA3W + ch3 * 512 + b * 16 + phys) * 2 + (hc & 1)] = __float2half(v);
            }
        }
    }
    __syncthreads();

    const int wm3 = wid & 1;
    const int wn3 = wid >> 1;
    float acc3[4][4];
#pragma unroll
    for (int jp = 0; jp < 4; jp++)
#pragma unroll
        for (int q = 0; q < 4; q++) acc3[jp][q] = 0.0f;

    for (int i = 0; i < 16; i++) {
        if (i < 14) { CP_WAIT1(); } else { CP_WAIT0(); }
        __syncthreads();
        const uint32_t* Br = smw + CW3R + (i & 1) * 2048;
        const uint32_t* Ab = smw + CA3W + i * 512;
#pragma unroll
        for (int s = 0; s < 2; s++) {
            int w0  = (s * 8 + t4) ^ (2 * g);
            int w1i = (s * 8 + 4 + t4) ^ (2 * g);
            int r0 = wm3 * 16;
            uint32_t a[4];
            a[0] = Ab[(r0 + g) * 16 + w0];
            a[1] = Ab[(r0 + g + 8) * 16 + w0];
            a[2] = Ab[(r0 + g) * 16 + w1i];
            a[3] = Ab[(r0 + g + 8) * 16 + w1i];
#pragma unroll
            for (int jp = 0; jp < 4; jp++) {
                int j8 = wn3 * 4 + jp;
                uint2 bf = *(const uint2*)(Br + (s * 16 + j8) * 64 + lane * 2);
                MMA_F16(acc3[jp], a, bf.x, bf.y);
            }
        }
        __syncthreads();
        if (i + 2 < 16) issueW3(i + 2);
    }

    // epilogue -> fp16 feat
#pragma unroll
    for (int jp = 0; jp < 4; jp++) {
        int colE = wn3 * 32 + jp * 8 + 2 * t4;
        float f0 = eluf(acc3[jp][0] + sm[CB3S + colE]);
        float f1 = eluf(acc3[jp][1] + sm[CB3S + colE + 1]);
        float f2 = eluf(acc3[jp][2] + sm[CB3S + colE]);
        float f3 = eluf(acc3[jp][3] + sm[CB3S + colE + 1]);
        int r = wm3 * 16 + g;
        *(uint32_t*)(g_feath + (size_t)(b0g + r) * 128 + colE)     = pack_h2(f0, f1);
        *(uint32_t*)(g_feath + (size_t)(b0g + r + 8) * 128 + colE) = pack_h2(f2, f3);
    }
}

// ---------------- fp16 LSTM-cell GEMM core ----------------
// smem words: B ring 3x4096 @0, A ring 3x1280 @12288 (stride-20 rows),
// bias @16128 (256), hw @16384 (1152). Total 17536 w = 70144 B.
// hs staging (64x66) and head staging (32x132) reuse B region post-mainloop.
#define ABUFW 1280
#define AOFF  12288
#define BIASO 16128
#define HWO   16384
#define SMEM_LSTM_WORDS 17536
#define SMEM_LSTM_BYTES (SMEM_LSTM_WORDS * 4)

__device__ __forceinline__ void lstm_core(
    int blk, float* sm, uint32_t smb,
    const float* __restrict__ Aps, int kps,          // fp32 source (ps), ld=256
    const __half* __restrict__ Aha, int kha,         // fp16 source a, ld=128
    const __half* __restrict__ Ahb, int khb,         // fp16 source b, ld=128
    const uint32_t* __restrict__ Wp, const float* __restrict__ biasp,
    const float* __restrict__ Ctprev, float* __restrict__ Ctout,
    __half* __restrict__ Hout,
    const __half* __restrict__ h2head, const float* __restrict__ headW,
    const float* __restrict__ headB, float* __restrict__ outPrev)
{
    uint32_t* smw = (uint32_t*)sm;
    float* bias_s = sm + BIASO;
    float* hw_s   = sm + HWO;

    const int tid  = threadIdx.x;
    const int wid  = tid >> 5;
    const int lane = tid & 31;
    const int g    = lane >> 2;
    const int t4   = lane & 3;
    const int wm   = wid & 1;
    const int wn2  = wid >> 1;
    const int half = blk & 1;
    const int row0 = (blk >> 1) * 64;
    const int ar   = tid >> 3;   // fp32 A row 0..31 (+32)
    const int aq   = tid & 7;

    bias_s[tid] = biasp[half * 256 + tid];
    if (h2head) {
        for (int idx = tid; idx < 1152; idx += 256) {
            int j = idx / 9, o = idx - j * 9;
            hw_s[idx] = headW[o * 128 + j];
        }
    }
    __syncthreads();

    float acc[2][8][4];
#pragma unroll
    for (int mt = 0; mt < 2; mt++)
#pragma unroll
        for (int j8 = 0; j8 < 8; j8++)
#pragma unroll
            for (int q = 0; q < 4; q++) acc[mt][j8][q] = 0.0f;

    const int nch = (kps + kha + khb) >> 5;

    // rotating ring state
    uint32_t* aw0 = smw + AOFF;
    uint32_t* aw1 = aw0 + ABUFW;
    uint32_t* aw2 = aw1 + ABUFW;
    const uint4* bq0 = (const uint4*)(smw) + wn2 * 256;
    const uint4* bq1 = (const uint4*)(smw + 4096) + wn2 * 256;
    const uint4* bq2 = (const uint4*)(smw + 8192) + wn2 * 256;
    uint32_t bb0 = smb + (uint32_t)tid * 16u;        // B cp.async dest (incl tid)
    uint32_t bb1 = bb0 + 16384u;
    uint32_t bb2 = bb1 + 16384u;
    uint32_t ab0 = smb + AOFF * 4;                   // A cp.async dest base
    uint32_t ab1 = ab0 + ABUFW * 4;
    uint32_t ab2 = ab1 + ABUFW * 4;

    auto ldgA = [&](int i, float4 v[2]) {
        const float* src = Aps + (size_t)(row0 + ar) * 256 + (i << 5) + aq * 4;
        v[0] = *(const float4*)src;
        v[1] = *(const float4*)(src + 32 * 256);
    };
    auto stsA = [&](uint32_t* ab, const float4 v[2]) {
        uint32_t* p = ab + ar * 20 + 2 * aq;
        p[0] = pack_h2(v[0].x, v[0].y);
        p[1] = pack_h2(v[0].z, v[0].w);
        p[640] = pack_h2(v[1].x, v[1].y);      // +32 rows * 20
        p[641] = pack_h2(v[1].z, v[1].w);
    };
    auto issueChunk = [&](int i, uint32_t bb, uint32_t ab) {
        const uint32_t* wsrc = Wp + (size_t)(i * 2 + half) * 4096;
#pragma unroll
        for (int it = 0; it < 4; it++) {
            CP16(bb + (uint32_t)it * 4096u, wsrc + (size_t)(it * 256 + tid) * 4);
        }
        int kb = i << 5;
        if (kb >= kps) {
            int kk = kb - kps;
            const __half* src = (kk < kha) ? (Aha + kk) : (Ahb + (kk - kha));
            int arow = tid >> 2, q = tid & 3;
            CP16(ab + (uint32_t)(arow * 20 + 4 * q) * 4,
                 src + (size_t)(row0 + arow) * 128 + q * 8);
        }
        CP_COMMIT();
    };

    // prologue
    float4 hold[2];
    if (kps > 0) {
        float4 a0v[2];
        ldgA(0, a0v);
        stsA(aw0, a0v);
    }
    issueChunk(0, bb0, ab0);
    if (nch > 1) {
        if (32 < kps) ldgA(1, hold);
        issueChunk(1, bb1, ab1);
    }

    const int r0a = wm * 32 + g;
    for (int i = 0; i < nch; i++) {
        if (i == nch - 1) { CP_WAIT0(); } else { CP_WAIT1(); }
        __syncthreads();
        if (i + 1 < nch && ((i + 1) << 5) < kps) stsA(aw1, hold);
        if (i + 2 < nch) {
            if (((i + 2) << 5) < kps) ldgA(i + 2, hold);
            issueChunk(i + 2, bb2, ab2);
        }

        const uint32_t* Aw = aw0;
        const uint4*    Bq = bq0;
#pragma unroll
        for (int s = 0; s < 2; s++) {
            uint4 bv[4];
#pragma unroll
            for (int jp = 0; jp < 4; jp++) bv[jp] = Bq[s * 128 + jp * 32 + lane];
            int wb = s * 8 + t4;
            uint32_t a[2][4];
#pragma unroll
            for (int mt = 0; mt < 2; mt++) {
                int rr = (r0a + mt * 16) * 20;
                a[mt][0] = Aw[rr + wb];
                a[mt][1] = Aw[rr + 160 + wb];
                a[mt][2] = Aw[rr + wb + 4];
                a[mt][3] = Aw[rr + 160 + wb + 4];
            }
#pragma unroll
            for (int jp = 0; jp < 4; jp++) {
                MMA_F16(acc[0][2 * jp],     a[0], bv[jp].x, bv[jp].y);
                MMA_F16(acc[1][2 * jp],     a[1], bv[jp].x, bv[jp].y);
                MMA_F16(acc[0][2 * jp + 1], a[0], bv[jp].z, bv[jp].w);
                MMA_F16(acc[1][2 * jp + 1], a[1], bv[jp].z, bv[jp].w);
            }
        }
        { uint32_t* t0 = aw0; aw0 = aw1; aw1 = aw2; aw2 = t0; }
        { const uint4* t0 = bq0; bq0 = bq1; bq1 = bq2; bq2 = t0; }
        { uint32_t t0 = bb0; bb0 = bb1; bb1 = bb2; bb2 = t0; }
        { uint32_t t0 = ab0; ab0 = ab1; ab1 = ab2; ab2 = t0; }
    }
    __syncthreads();   // B region free -> hs staging

    // ---- shuffle epilogue ----
    float* hs = sm;    // [64][66]
    const bool odd = (t4 & 1) != 0;
    const int jc0 = wn2 * 16 + (t4 >> 1);
#pragma unroll
    for (int mt = 0; mt < 2; mt++) {
#pragma unroll
        for (int j8 = 0; j8 < 8; j8++) {
            int n0 = wn2 * 64 + j8 * 8 + 2 * t4;
            float b0 = bias_s[n0], b1 = bias_s[n0 + 1];
            float v0 = acc[mt][j8][0] + b0;
            float v1 = acc[mt][j8][1] + b1;
            float v2 = acc[mt][j8][2] + b0;
            float v3 = acc[mt][j8][3] + b1;
            float e0, e1, e2, e3;
            if (odd) { e0 = tanhx(v0); e1 = sigf(v1); e2 = tanhx(v2); e3 = sigf(v3); }
            else     { e0 = sigf(v0);  e1 = sigf(v1); e2 = sigf(v2);  e3 = sigf(v3); }
            float r0 = __shfl_xor_sync(0xFFFFFFFFu, e0, 1);
            float r1 = __shfl_xor_sync(0xFFFFFFFFu, e1, 1);
            float r2 = __shfl_xor_sync(0xFFFFFFFFu, e2, 1);
            float r3 = __shfl_xor_sync(0xFFFFFFFFu, e3, 1);
            if (odd) {
                int j = jc0 + j8 * 2;
                int colg = half * 64 + j;
                int rl = wm * 32 + mt * 16 + g;
                size_t base = (size_t)colg * Bn + row0 + rl;
                float cpA = Ctprev ? Ctprev[base] : 0.0f;
                float cpB = Ctprev ? Ctprev[base + 8] : 0.0f;
                float cA = r1 * cpA + r0 * e0;
                float cB = r3 * cpB + r2 * e2;
                Ctout[base] = cA;
                Ctout[base + 8] = cB;
                hs[rl * 66 + j] = e1 * tanhx(cA);
                hs[(rl + 8) * 66 + j] = e3 * tanhx(cB);
            }
        }
    }
    __syncthreads();

    // coalesced fp16 h write
#pragma unroll
    for (int it = 0; it < 2; it++) {
        int idx = tid + it * 256;
        int r = idx >> 3, q = idx & 7;
        const float* hr = hs + r * 66 + q * 8;
        uint4 o;
        o.x = pack_h2(hr[0], hr[1]);
        o.y = pack_h2(hr[2], hr[3]);
        o.z = pack_h2(hr[4], hr[5]);
        o.w = pack_h2(hr[6], hr[7]);
        *(uint4*)(Hout + (size_t)(row0 + r) * 128 + half * 64 + q * 8) = o;
    }

    // head for an older step's h2 (32 rows per CTA)
    if (h2head) {
        __syncthreads();
        const int hr0 = row0 + half * 32;
#pragma unroll
        for (int it = 0; it < 2; it++) {
            int idx = tid + it * 256;
            int r = idx >> 4, hq = idx & 15;
            uint4 v = *(const uint4*)(h2head + (size_t)(hr0 + r) * 128 + hq * 8);
            const __half2* hp = (const __half2*)&v;
#pragma unroll
            for (int k = 0; k < 4; k++) {
                float2 f = __half22float2(hp[k]);
                sm[r * 132 + hq * 8 + 2 * k]     = f.x;
                sm[r * 132 + hq * 8 + 2 * k + 1] = f.y;
            }
        }
        __syncthreads();
        for (int idx = tid; idx < 288; idx += 256) {
            int r = idx / 9, o = idx - r * 9;
            float s = headB[o];
            const float* hr = sm + r * 132;
#pragma unroll 8
            for (int jj = 0; jj < 128; jj++) s += hr[jj] * hw_s[jj * 9 + o];
            outPrev[(size_t)(hr0 + r) * 9 + o] = s;
        }
    }
}

__global__ __launch_bounds__(256, 2)
void lstm_single_kernel(const float* __restrict__ Aps, int kps,
                        const __half* __restrict__ Aha, int kha,
                        const __half* __restrict__ Ahb, int khb,
                        const uint32_t* __restrict__ Wp, const float* __restrict__ biasp,
                        const float* __restrict__ Ctprev, float* __restrict__ Ctout,
                        __half* __restrict__ Hout)
{
    extern __shared__ float sm[];
    uint32_t smb = smem_u32(sm);
    lstm_core(blockIdx.x, sm, smb, Aps, kps, Aha, kha, Ahb, khb, Wp, biasp,
              Ctprev, Ctout, Hout, nullptr, nullptr, nullptr, nullptr);
}

__global__ __launch_bounds__(256, 2)
void lstm_merged_kernel(const float* __restrict__ ps_s,
                        const __half* __restrict__ h1prev, __half* __restrict__ h1out,
                        const __half* __restrict__ h2old, int kh2, __half* __restrict__ h2out,
                        const uint32_t* __restrict__ W1, const float* __restrict__ b1,
                        const uint32_t* __restrict__ W2, const float* __restrict__ b2,
                        float* __restrict__ c1t, const float* __restrict__ c2tprev,
                        float* __restrict__ c2t,
                        const __half* __restrict__ h2head, const float* __restrict__ headW,
                        const float* __restrict__ headB, float* __restrict__ outPrev)
{
    extern __shared__ float sm[];
    uint32_t smb = smem_u32(sm);
    if (blockIdx.x < 1024) {
        lstm_core(blockIdx.x, sm, smb, ps_s, 256, h1prev, 128, nullptr, 0,
                  W1, b1, c1t, c1t, h1out, h2head, headW, headB, outPrev);
    } else {
        lstm_core(blockIdx.x - 1024, sm, smb, nullptr, 0, h1prev, 128, h2old, kh2,
                  W2, b2, c2tprev, c2t, h2out, nullptr, nullptr, nullptr, nullptr);
    }
}

// ---------------- final head kernel: steps 15 and 16 (fp16 h2) ----------------
__global__ __launch_bounds__(256)
void head2_kernel(const __half* __restrict__ h2a, const __half* __restrict__ h2b,
                  const float* __restrict__ headW, const float* __restrict__ headB,
                  float* __restrict__ outA, float* __restrict__ outB)
{
    __shared__ float hs[64 * 132];
    __shared__ float hw[1152];
    const int t = threadIdx.x;
    const bool second = blockIdx.x >= 512;
    const __half* h2 = second ? h2b : h2a;
    float* outp = second ? outB : outA;
    const int r0 = (second ? (blockIdx.x - 512) : blockIdx.x) * 64;
    for (int idx = t; idx < 1152; idx += 256) {
        int j = idx / 9, o = idx - j * 9;
        hw[idx] = headW[o * 128 + j];
    }
#pragma unroll
    for (int it = 0; it < 4; it++) {
        int idx = t + it * 256;
        int r = idx >> 4, hq = idx & 15;
        uint4 v = *(const uint4*)(h2 + (size_t)(r0 + r) * 128 + hq * 8);
        const __half2* hp = (const __half2*)&v;
#pragma unroll
        for (int k = 0; k < 4; k++) {
            float2 f = __half22float2(hp[k]);
            hs[r * 132 + hq * 8 + 2 * k]     = f.x;
            hs[r * 132 + hq * 8 + 2 * k + 1] = f.y;
        }
    }
    __syncthreads();
    for (int idx = t; idx < 576; idx += 256) {
        int r = idx / 9, o = idx - r * 9;
        float s = headB[o];
        const float* hr = hs + r * 132;
#pragma unroll 8
        for (int jj = 0; jj < 128; jj++) s += hr[jj] * hw[jj * 9 + o];
        outp[(size_t)(r0 + r) * 9 + o] = s;
    }
}

// ---------------- launch ----------------
extern "C" void kernel_launch(void* const* d_in, const int* in_sizes, int n_in,
                              void* d_out, int out_size) {
    const float* x        = (const float*)d_in[0];
    const float* ps       = (const float*)d_in[1];
    const float* conv1_w  = (const float*)d_in[2];
    const float* conv1_b  = (const float*)d_in[3];
    const float* conv2_w  = (const float*)d_in[4];
    const float* conv2_b  = (const float*)d_in[5];
    const float* conv3_w  = (const float*)d_in[6];
    const float* conv3_b  = (const float*)d_in[7];
    const float* w_ih1    = (const float*)d_in[8];
    const float* w_hh1    = (const float*)d_in[9];
    const float* b_ih1    = (const float*)d_in[10];
    const float* b_hh1    = (const float*)d_in[11];
    const float* w_ih2    = (const float*)d_in[12];
    const float* w_hh2    = (const float*)d_in[13];
    const float* b_ih2    = (const float*)d_in[14];
    const float* b_hh2    = (const float*)d_in[15];
    const float* head_w   = (const float*)d_in[16];
    const float* head_b   = (const float*)d_in[17];
    float* out = (float*)d_out;

    cudaFuncSetAttribute(conv_kernel, cudaFuncAttributeMaxDynamicSharedMemorySize, CONV_SMEM_BYTES);
    cudaFuncSetAttribute(lstm_single_kernel, cudaFuncAttributeMaxDynamicSharedMemorySize, SMEM_LSTM_BYTES);
    cudaFuncSetAttribute(lstm_merged_kernel, cudaFuncAttributeMaxDynamicSharedMemorySize, SMEM_LSTM_BYTES);

    __half *feath, *h1h, *h2h;
    float *c1t, *c2t, *b1p, *b2p;
    uint32_t *W1h, *W2h;
    cudaGetSymbolAddress((void**)&feath, g_feath);
    cudaGetSymbolAddress((void**)&h1h, g_h1h);
    cudaGetSymbolAddress((void**)&h2h, g_h2h);
    cudaGetSymbolAddress((void**)&c1t, g_c1t);
    cudaGetSymbolAddress((void**)&c2t, g_c2t);
    cudaGetSymbolAddress((void**)&W1h, g_W1h);
    cudaGetSymbolAddress((void**)&W2h, g_W2h);
    cudaGetSymbolAddress((void**)&b1p, g_b1p);
    cudaGetSymbolAddress((void**)&b2p, g_b2p);

    const int prep_total = 12 * 8192 + 8 * 8192 + 1024 + 7168 + 32768;
    prep_kernel<<<(prep_total + 255) / 256, 256>>>(w_ih1, w_hh1, b_ih1, b_hh1,
                                                   w_ih2, w_hh2, b_ih2, b_hh2,
                                                   conv2_w, conv3_w);

    conv_kernel<<<Bn / 32, 256, CONV_SMEM_BYTES>>>(x, conv1_w, conv1_b, conv2_b, conv3_b);

    // L1_0: A = feat (fp16), cold -> h1h[0], c1t
    lstm_single_kernel<<<1024, 256, SMEM_LSTM_BYTES>>>(
        nullptr, 0, feath, 128, nullptr, 0, W1h, b1p, nullptr, c1t, h1h);

    // merged steps: launch s = [L1_s | L2_{s-1}]
    for (int s = 1; s <= Tn; s++) {
        const float* A       = ps + (size_t)(s - 1) * Bn * 256;
        const __half* h1prev = h1h + (size_t)((s - 1) & 1) * BH;
        __half*       h1out  = h1h + (size_t)(s & 1) * BH;
        const __half* h2old  = (s >= 2) ? (h2h + (size_t)(s & 1) * BH) : nullptr;
        __half*       h2out  = h2h + (size_t)((s - 1) & 1) * BH;
        lstm_merged_kernel<<<2048, 256, SMEM_LSTM_BYTES>>>(
            A, h1prev, h1out, h2old, (s >= 2) ? 128 : 0, h2out,
            W1h, b1p, W2h, b2p,
            c1t, (s >= 2) ? c2t : nullptr, c2t,
            h2old, head_w, head_b,
            (s >= 2) ? (out + (size_t)(s - 2) * Bn * 9) : nullptr);
    }

    // L2_16: h1_16 = h1h[0], h2_15 = h2h[1] -> h2h[0]
    lstm_single_kernel<<<1024, 256, SMEM_LSTM_BYTES>>>(
        nullptr, 0, h1h, 128, h2h + BH, 128, W2h, b2p, c2t, c2t, h2h);

    // heads for steps 15 (h2h[1]) and 16 (h2h[0])
    head2_kernel<<<1024, 256>>>(h2h + BH, h2h, head_w, head_b,
                                out + (size_t)15 * Bn * 9, out + (size_t)16 * Bn * 9);
}

// round 14
// speedup vs baseline: 1.2253x; 1.2253x over previous
#include <cuda_runtime.h>
#include <cuda_fp16.h>
#include <math.h>
#include <stdint.h>

#define Bn 32768
#define Tn 16
#define BH (Bn * 128)

// ---------------- device scratch ----------------
__device__ __align__(16) __half g_feath[BH];
__device__ __align__(16) __half g_h1h[2 * BH];
__device__ __align__(16) __half g_h2h[2 * BH];
__device__ float    g_c1[BH];    // row-major, in-place
__device__ float    g_c2[BH];
__device__ __align__(16) uint32_t g_W1h[12 * 8192];
__device__ __align__(16) uint32_t g_W2h[8 * 8192];
__device__ __align__(16) uint32_t g_W2c[7168];
__device__ __align__(16) uint32_t g_W3c[32768];
__device__ float    g_b1p[512];   // gate-interleaved n' = 4j+gate
__device__ float    g_b2p[512];

// ---------------- helpers ----------------
__device__ __forceinline__ uint32_t smem_u32(const void* p) {
    uint32_t r;
    asm("{ .reg .u64 t; cvta.to.shared.u64 t, %1; cvt.u32.u64 %0, t; }" : "=r"(r) : "l"(p));
    return r;
}
#define CP16(dst, src) asm volatile("cp.async.cg.shared.global [%0], [%1], 16;" :: "r"(dst), "l"(src))
#define CP8(dst, src)  asm volatile("cp.async.ca.shared.global [%0], [%1], 8;"  :: "r"(dst), "l"(src))
#define CP_COMMIT()    asm volatile("cp.async.commit_group;" ::: "memory")
#define CP_WAIT0()     asm volatile("cp.async.wait_group 0;" ::: "memory")
#define CP_WAIT1()     asm volatile("cp.async.wait_group 1;" ::: "memory")

#define MMA_F16(d, a, b0v, b1v) \
    asm volatile("mma.sync.aligned.m16n8k16.row.col.f32.f16.f16.f32 " \
        "{%0,%1,%2,%3}, {%4,%5,%6,%7}, {%8,%9}, {%0,%1,%2,%3};" \
        : "+f"((d)[0]), "+f"((d)[1]), "+f"((d)[2]), "+f"((d)[3]) \
        : "r"((a)[0]), "r"((a)[1]), "r"((a)[2]), "r"((a)[3]), "r"(b0v), "r"(b1v))

__device__ __forceinline__ uint32_t pack_h2(float lo, float hi) {
    __half2 h = __floats2half2_rn(lo, hi);
    uint32_t u;
    memcpy(&u, &h, 4);
    return u;
}
__device__ __forceinline__ float sigf(float x) { return __fdividef(1.0f, 1.0f + __expf(-x)); }
__device__ __forceinline__ float tanhx(float x) { return __fdividef(2.0f, 1.0f + __expf(-2.0f * x)) - 1.0f; }
__device__ __forceinline__ float eluf(float x) { return x > 0.0f ? x : expm1f(x); }

// ---------------- weight prep (identical fragment orders to R12) ----------------
__global__ void prep_kernel(const float* __restrict__ w_ih1, const float* __restrict__ w_hh1,
                            const float* __restrict__ b_ih1, const float* __restrict__ b_hh1,
                            const float* __restrict__ w_ih2, const float* __restrict__ w_hh2,
                            const float* __restrict__ b_ih2, const float* __restrict__ b_hh2,
                            const float* __restrict__ w2c, const float* __restrict__ w3c) {
    int i = blockIdx.x * blockDim.x + threadIdx.x;
    const int total1 = 12 * 8192;
    const int total2 = 8 * 8192;
    const int base3  = total1 + total2 + 1024;
    if (i < total1 + total2) {
        int li = (i < total1) ? i : i - total1;
        int w    = li & 3;
        int lane = (li >> 2) & 31;
        int jp   = (li >> 7) & 3;
        int s    = (li >> 9) & 1;
        int wn2  = (li >> 10) & 3;
        int half = (li >> 12) & 1;
        int ch   = li >> 13;
        int g = lane >> 2, t4 = lane & 3;
        int j8 = jp * 2 + (w >> 1);
        int k  = ch * 32 + s * 16 + 8 * (w & 1) + 2 * t4;
        int np = half * 256 + wn2 * 64 + j8 * 8 + g;
        int j = np >> 2, gate = np & 3;
        int n = gate * 128 + j;
        float f0, f1;
        if (i < total1) {
            if (k < 256) { f0 = w_ih1[n * 256 + k];        f1 = w_ih1[n * 256 + k + 1]; }
            else         { f0 = w_hh1[n * 128 + k - 256];  f1 = w_hh1[n * 128 + k - 255]; }
            g_W1h[li] = pack_h2(f0, f1);
        } else {
            if (k < 128) { f0 = w_ih2[n * 128 + k];        f1 = w_ih2[n * 128 + k + 1]; }
            else         { f0 = w_hh2[n * 128 + k - 128];  f1 = w_hh2[n * 128 + k - 127]; }
            g_W2h[li] = pack_h2(f0, f1);
        }
    } else if (i < total1 + total2 + 512) {
        int np = i - total1 - total2;
        int j = np >> 2, gate = np & 3;
        int n = gate * 128 + j;
        g_b1p[np] = b_ih1[n] + b_hh1[n];
    } else if (i < base3) {
        int np = i - total1 - total2 - 512;
        int j = np >> 2, gate = np & 3;
        int n = gate * 128 + j;
        g_b2p[np] = b_ih2[n] + b_hh2[n];
    } else if (i < base3 + 7168) {
        int wi = i - base3;
        int w01  = wi & 1;
        int lane = (wi >> 1) & 31;
        int j8   = (wi >> 6) & 7;
        int sc   = wi >> 9;
        int g = lane >> 2, t4 = lane & 3;
        int n = j8 * 8 + g;
        int k0 = sc * 16 + 2 * t4 + 8 * w01;
        g_W2c[wi] = pack_h2(w2c[n * 224 + k0], w2c[n * 224 + k0 + 1]);
    } else if (i < base3 + 7168 + 32768) {
        int wi = i - base3 - 7168;
        int w01  = wi & 1;
        int lane = (wi >> 1) & 31;
        int j8   = (wi >> 6) & 15;
        int sc   = wi >> 10;
        int g = lane >> 2, t4 = lane & 3;
        int n = j8 * 8 + g;
        int k0 = sc * 16 + 2 * t4 + 8 * w01;
        float f0, f1;
        {
            int ci2 = k0 >> 3, p = k0 & 7;
            f0 = (p < 7) ? w3c[n * 448 + ci2 * 7 + p] : 0.0f;
        }
        {
            int k1 = k0 + 1;
            int ci2 = k1 >> 3, p = k1 & 7;
            f1 = (p < 7) ? w3c[n * 448 + ci2 * 7 + p] : 0.0f;
        }
        g_W3c[wi] = pack_h2(f0, f1);
    }
}

// ---------------- conv stack (R12 structure, fp16 feat output) ----------------
#define CXS   0
#define CW2F  640
#define CB2S  7808
#define CB3S  7872
#define CA3W  8000
#define CW3R  16192
#define CY1H  20288
#define CA2W  26944
#define CW1S  55616
#define CB1S  55840
#define CONV_SMEM_WORDS 55872
#define CONV_SMEM_BYTES (CONV_SMEM_WORDS * 4)

__global__ __launch_bounds__(256, 1)
void conv_kernel(const float* __restrict__ x,
                 const float* __restrict__ w1, const float* __restrict__ b1,
                 const float* __restrict__ b2, const float* __restrict__ b3) {
    extern __shared__ float sm[];
    __half* smh = (__half*)sm;
    uint32_t* smw = (uint32_t*)sm;
    uint32_t smb = smem_u32(sm);

    const int t    = threadIdx.x;
    const int lane = t & 31;
    const int wid  = t >> 5;
    const int g    = lane >> 2;
    const int t4   = lane & 3;
    const int b0g  = blockIdx.x * 32;

#pragma unroll
    for (int it = 0; it < 7; it++) {
        int gi = it * 1024 + t * 4;
        CP16(smb + (CW2F + gi) * 4, g_W2c + gi);
    }
    CP_COMMIT();

    for (int idx = t; idx < 608; idx += 256) {
        int b = idx / 19, q = idx - b * 19;
        sm[CXS + b * 20 + q] = x[(size_t)(b0g + b) * 19 + q];
    }
    if (t < 224) sm[CW1S + t] = w1[t];
    if (t < 32)  sm[CB1S + t] = b1[t];
    if (t < 64)  sm[CB2S + t] = b2[t];
    if (t < 128) sm[CB3S + t] = b3[t];
    __syncthreads();

    for (int idx = t; idx < 13312; idx += 256) {
        int b = idx / 416;
        int rem = idx - b * 416;
        int ci = rem / 13, q = rem - ci * 13;
        float s = sm[CB1S + ci];
#pragma unroll
        for (int k = 0; k < 7; k++) s += sm[CXS + b * 20 + q + k] * sm[CW1S + ci * 7 + k];
        smh[CY1H * 2 + idx] = __float2half(eluf(s));
    }
    for (int idx = t; idx < 8192; idx += 256) sm[CA3W + idx] = 0.0f;
    __syncthreads();

    {
        const int r = t;
        const int b = r >> 3, p = r & 7;
        const int xr = 2 * (r & 7);
        if (p < 7) {
            const __half* y1r = smh + CY1H * 2 + b * 416 + p;
            int c = 0;
            for (int ci = 0; ci < 32; ci++) {
                const __half* yq = y1r + ci * 13;
#pragma unroll
                for (int k = 0; k < 7; k++, c++) {
                    int ch = c >> 5, hc = c & 31;
                    int phys = (hc >> 1) ^ xr;
                    smh[(CA2W + ch * 4096 + r * 16 + phys) * 2 + (hc & 1)] = yq[k];
                }
            }
        } else {
            const __half z = __float2half(0.0f);
            for (int c = 0; c < 224; c++) {
                int ch = c >> 5, hc = c & 31;
                int phys = (hc >> 1) ^ xr;
                smh[(CA2W + ch * 4096 + r * 16 + phys) * 2 + (hc & 1)] = z;
            }
        }
    }
    CP_WAIT0();
    __syncthreads();

    auto issueW3 = [&](int i) {
        const uint32_t* src = g_W3c + i * 2048;
        uint32_t dst = smb + (CW3R + (i & 1) * 2048) * 4;
#pragma unroll
        for (int it = 0; it < 2; it++) {
            int gi = it * 1024 + t * 4;
            CP16(dst + gi * 4, src + gi);
        }
        CP_COMMIT();
    };
    issueW3(0);
    issueW3(1);

    const int wm2 = wid & 3;
    const int wn  = wid >> 2;
    float acc2[4][4][4];
#pragma unroll
    for (int mt = 0; mt < 4; mt++)
#pragma unroll
        for (int jp = 0; jp < 4; jp++)
#pragma unroll
            for (int q = 0; q < 4; q++) acc2[mt][jp][q] = 0.0f;

    for (int ch = 0; ch < 7; ch++) {
        const uint32_t* Ab = smw + CA2W + ch * 4096;
#pragma unroll
        for (int s = 0; s < 2; s++) {
            uint2 bf[4];
#pragma unroll
            for (int jp = 0; jp < 4; jp++) {
                int j8 = wn * 4 + jp;
                bf[jp] = *(const uint2*)(smw + CW2F + ((ch * 2 + s) * 8 + j8) * 64 + lane * 2);
            }
            int w0  = (s * 8 + t4) ^ (2 * g);
            int w1i = (s * 8 + 4 + t4) ^ (2 * g);
#pragma unroll
            for (int mt = 0; mt < 4; mt++) {
                int r0 = wm2 * 64 + mt * 16;
                uint32_t a[4];
                a[0] = Ab[(r0 + g) * 16 + w0];
                a[1] = Ab[(r0 + g + 8) * 16 + w0];
                a[2] = Ab[(r0 + g) * 16 + w1i];
                a[3] = Ab[(r0 + g + 8) * 16 + w1i];
#pragma unroll
                for (int jp = 0; jp < 4; jp++)
                    MMA_F16(acc2[mt][jp], a, bf[jp].x, bf[jp].y);
            }
        }
    }

#pragma unroll
    for (int mt = 0; mt < 4; mt++) {
#pragma unroll
        for (int q = 0; q < 4; q++) {
            int r = wm2 * 64 + mt * 16 + g + ((q >> 1) << 3);
            int p = r & 7;
            if (p == 7) continue;
            int b = r >> 3;
            int xr = 2 * (b & 7);
#pragma unroll
            for (int jp = 0; jp < 4; jp++) {
                int n = wn * 32 + jp * 8 + 2 * t4 + (q & 1);
                float v = eluf(acc2[mt][jp][q] + sm[CB2S + n]);
                int c3 = n * 8 + p;
                int ch3 = c3 >> 5, hc = c3 & 31;
                int phys = (hc >> 1) ^ xr;
                smh[(CA3W + ch3 * 512 + b * 16 + phys) * 2 + (hc & 1)] = __float2half(v);
            }
        }
    }
    __syncthreads();

    const int wm3 = wid & 1;
    const int wn3 = wid >> 1;
    float acc3[4][4];
#pragma unroll
    for (int jp = 0; jp < 4; jp++)
#pragma unroll
        for (int q = 0; q < 4; q++) acc3[jp][q] = 0.0f;

    for (int i = 0; i < 16; i++) {
        if (i < 14) { CP_WAIT1(); } else { CP_WAIT0(); }
        __syncthreads();
        const uint32_t* Br = smw + CW3R + (i & 1) * 2048;
        const uint32_t* Ab = smw + CA3W + i * 512;
#pragma unroll
        for (int s = 0; s < 2; s++) {
            int w0  = (s * 8 + t4) ^ (2 * g);
            int w1i = (s * 8 + 4 + t4) ^ (2 * g);
            int r0 = wm3 * 16;
            uint32_t a[4];
            a[0] = Ab[(r0 + g) * 16 + w0];
            a[1] = Ab[(r0 + g + 8) * 16 + w0];
            a[2] = Ab[(r0 + g) * 16 + w1i];
            a[3] = Ab[(r0 + g + 8) * 16 + w1i];
#pragma unroll
            for (int jp = 0; jp < 4; jp++) {
                int j8 = wn3 * 4 + jp;
                uint2 bf = *(const uint2*)(Br + (s * 16 + j8) * 64 + lane * 2);
                MMA_F16(acc3[jp], a, bf.x, bf.y);
            }
        }
        __syncthreads();
        if (i + 2 < 16) issueW3(i + 2);
    }

    // epilogue -> fp16 feat
#pragma unroll
    for (int jp = 0; jp < 4; jp++) {
        int colE = wn3 * 32 + jp * 8 + 2 * t4;
        float f0 = eluf(acc3[jp][0] + sm[CB3S + colE]);
        float f1 = eluf(acc3[jp][1] + sm[CB3S + colE + 1]);
        float f2 = eluf(acc3[jp][2] + sm[CB3S + colE]);
        float f3 = eluf(acc3[jp][3] + sm[CB3S + colE + 1]);
        int r = wm3 * 16 + g;
        *(uint32_t*)(g_feath + (size_t)(b0g + r) * 128 + colE)     = pack_h2(f0, f1);
        *(uint32_t*)(g_feath + (size_t)(b0g + r + 8) * 128 + colE) = pack_h2(f2, f3);
    }
}

// ---------------- fp16 LSTM-cell GEMM core (R12 layout; fp16 h via 8B cp.async) ----------------
#define SMEM_LSTM_WORDS 18048
#define SMEM_LSTM_BYTES (SMEM_LSTM_WORDS * 4)
#define AOFF 12288
#define BIASO 16640
#define HWO  16896

__device__ __forceinline__ void lstm_core(
    int blk, float* sm, uint32_t smb,
    const float* __restrict__ Aps, int kps,          // fp32 ps, ld=256
    const __half* __restrict__ Aha, int kha,         // fp16 source a, ld=128
    const __half* __restrict__ Ahb, int khb,         // fp16 source b, ld=128
    const uint32_t* __restrict__ Wp, const float* __restrict__ biasp,
    const float* __restrict__ Cprev, float* __restrict__ Cout,
    __half* __restrict__ Hout,
    const __half* __restrict__ h2head, const float* __restrict__ headW,
    const float* __restrict__ headB, float* __restrict__ outPrev)
{
    uint32_t* smw = (uint32_t*)sm;
    float* bias_s = sm + BIASO;
    float* hw_s   = sm + HWO;

    const int tid  = threadIdx.x;
    const int wid  = tid >> 5;
    const int lane = tid & 31;
    const int g    = lane >> 2;
    const int t4   = lane & 3;
    const int wm   = wid & 1;
    const int wn2  = wid >> 1;
    const int half = blk & 1;
    const int row0 = (blk >> 1) * 64;
    const int ar   = tid >> 3;
    const int aq   = tid & 7;

    bias_s[tid] = biasp[half * 256 + tid];
    if (h2head) {
        for (int idx = tid; idx < 1152; idx += 256) {
            int j = idx / 9, o = idx - j * 9;
            hw_s[idx] = headW[o * 128 + j];
        }
    }
    __syncthreads();

    float acc[2][8][4];
#pragma unroll
    for (int mt = 0; mt < 2; mt++)
#pragma unroll
        for (int j8 = 0; j8 < 8; j8++)
#pragma unroll
            for (int q = 0; q < 4; q++) acc[mt][j8][q] = 0.0f;

    const int nch = (kps + kha + khb) >> 5;
    const int awsw = (2 * aq) ^ (2 * (ar & 7));

    // rings
    const uint32_t* aw0 = smw + AOFF;
    const uint32_t* aw1 = aw0 + 1024;
    const uint32_t* aw2 = aw1 + 1024;
    const uint4* bq0 = (const uint4*)(smw) + wn2 * 256;
    const uint4* bq1 = (const uint4*)(smw + 4096) + wn2 * 256;
    const uint4* bq2 = (const uint4*)(smw + 8192) + wn2 * 256;
    uint32_t* sp0 = smw + AOFF + ar * 16 + awsw;
    uint32_t* sp1 = sp0 + 1024;
    uint32_t* sp2 = sp1 + 1024;
    uint32_t bb0 = smb + (uint32_t)tid * 16u;
    uint32_t bb1 = bb0 + 16384u;
    uint32_t bb2 = bb1 + 16384u;
    uint32_t ab0 = smb + AOFF * 4;
    uint32_t ab1 = ab0 + 4096u;
    uint32_t ab2 = ab1 + 4096u;

    auto ldgA = [&](int i, float4 v[2]) {
        const float* src = Aps + (size_t)(row0 + ar) * 256 + (i << 5) + aq * 4;
        v[0] = *(const float4*)src;
        v[1] = *(const float4*)(src + 32 * 256);
    };
    auto stsA = [&](uint32_t* p, const float4 v[2]) {
        p[0]   = pack_h2(v[0].x, v[0].y);
        p[1]   = pack_h2(v[0].z, v[0].w);
        p[512] = pack_h2(v[1].x, v[1].y);
        p[513] = pack_h2(v[1].z, v[1].w);
    };
    auto issueChunk = [&](int i, uint32_t bb, uint32_t ab) {
        const uint32_t* wsrc = Wp + (size_t)(i * 2 + half) * 4096;
#pragma unroll
        for (int it = 0; it < 4; it++) {
            CP16(bb + (uint32_t)it * 4096u, wsrc + (size_t)(it * 256 + tid) * 4);
        }
        int kb = i << 5;
        if (kb >= kps) {
            int kk = kb - kps;
            const __half* src = (kk < kha) ? (Aha + kk) : (Ahb + (kk - kha));
#pragma unroll
            for (int it = 0; it < 2; it++) {
                int e = it * 256 + tid;
                int r = e >> 3, q8 = e & 7;
                uint32_t w = (uint32_t)(r * 16 + ((2 * q8) ^ (2 * (r & 7))));
                CP8(ab + w * 4u, src + (size_t)(row0 + r) * 128 + q8 * 4);
            }
        }
        CP_COMMIT();
    };

    // prologue
    float4 hold[2];
    if (kps > 0) {
        float4 a0v[2];
        ldgA(0, a0v);
        stsA(sp0, a0v);
    }
    issueChunk(0, bb0, ab0);
    if (nch > 1) {
        if (32 < kps) ldgA(1, hold);
        issueChunk(1, bb1, ab1);
    }

    const int xg = 2 * g;
    const int r0a = wm * 32 + g;
    for (int i = 0; i < nch; i++) {
        if (i == nch - 1) { CP_WAIT0(); } else { CP_WAIT1(); }
        __syncthreads();
        if (i + 1 < nch && ((i + 1) << 5) < kps) stsA(sp1, hold);
        if (i + 2 < nch) {
            if (((i + 2) << 5) < kps) ldgA(i + 2, hold);
            issueChunk(i + 2, bb2, ab2);
        }

        const uint32_t* Aw = aw0;
        const uint4*    Bq = bq0;

#pragma unroll
        for (int s = 0; s < 2; s++) {
            uint4 bv[4];
#pragma unroll
            for (int jp = 0; jp < 4; jp++) bv[jp] = Bq[s * 128 + jp * 32 + lane];
            uint32_t a[2][4];
#pragma unroll
            for (int mt = 0; mt < 2; mt++) {
                int r0 = r0a + mt * 16;
                int w0 = (s * 8 + t4) ^ xg;
                int w1 = (s * 8 + 4 + t4) ^ xg;
                a[mt][0] = Aw[r0 * 16 + w0];
                a[mt][1] = Aw[(r0 + 8) * 16 + w0];
                a[mt][2] = Aw[r0 * 16 + w1];
                a[mt][3] = Aw[(r0 + 8) * 16 + w1];
            }
#pragma unroll
            for (int jp = 0; jp < 4; jp++) {
                MMA_F16(acc[0][2 * jp],     a[0], bv[jp].x, bv[jp].y);
                MMA_F16(acc[1][2 * jp],     a[1], bv[jp].x, bv[jp].y);
                MMA_F16(acc[0][2 * jp + 1], a[0], bv[jp].z, bv[jp].w);
                MMA_F16(acc[1][2 * jp + 1], a[1], bv[jp].z, bv[jp].w);
            }
        }
        { const uint32_t* t0 = aw0; aw0 = aw1; aw1 = aw2; aw2 = t0; }
        { const uint4* t0 = bq0; bq0 = bq1; bq1 = bq2; bq2 = t0; }
        { uint32_t* t0 = sp0; sp0 = sp1; sp1 = sp2; sp2 = t0; }
        { uint32_t t0 = bb0; bb0 = bb1; bb1 = bb2; bb2 = t0; }
        { uint32_t t0 = ab0; ab0 = ab1; ab1 = ab2; ab2 = t0; }
    }
    __syncthreads();

    // stage gates to [64][260] (R12)
#pragma unroll
    for (int mt = 0; mt < 2; mt++) {
        int row = wm * 32 + mt * 16 + g;
#pragma unroll
        for (int j8 = 0; j8 < 8; j8++) {
            int col = wn2 * 64 + j8 * 8 + 2 * t4;
            sm[row * 260 + col]           = acc[mt][j8][0];
            sm[row * 260 + col + 1]       = acc[mt][j8][1];
            sm[(row + 8) * 260 + col]     = acc[mt][j8][2];
            sm[(row + 8) * 260 + col + 1] = acc[mt][j8][3];
        }
    }
    __syncthreads();

    // cell epilogue (R12; gate-interleaved cols so float4 = {i,f,g,o} of one j)
    {
        const int j0 = tid & 63;
        const int rg = tid >> 6;
        const int col = half * 64 + j0;
        const float4 bb = *(const float4*)(bias_s + 4 * j0);
#pragma unroll
        for (int rr = 0; rr < 16; rr++) {
            int r = rg * 16 + rr;
            int row = row0 + r;
            float4 gv = *(const float4*)(sm + r * 260 + 4 * j0);
            float gi = gv.x + bb.x;
            float gf = gv.y + bb.y;
            float gg = gv.z + bb.z;
            float go = gv.w + bb.w;
            float cp = Cprev ? Cprev[(size_t)row * 128 + col] : 0.0f;
            float c  = sigf(gf) * cp + sigf(gi) * tanhx(gg);
            float h  = sigf(go) * tanhx(c);
            Cout[(size_t)row * 128 + col] = c;
            Hout[(size_t)row * 128 + col] = __float2half(h);
        }
    }

    // head for an older step's h2 (32 rows per CTA)
    if (h2head) {
        __syncthreads();
        const int hr0 = row0 + half * 32;
#pragma unroll
        for (int it = 0; it < 2; it++) {
            int idx = tid + it * 256;
            int r = idx >> 4, hq = idx & 15;
            uint4 v = *(const uint4*)(h2head + (size_t)(hr0 + r) * 128 + hq * 8);
            const __half2* hp = (const __half2*)&v;
#pragma unroll
            for (int k = 0; k < 4; k++) {
                float2 f = __half22float2(hp[k]);
                sm[r * 132 + hq * 8 + 2 * k]     = f.x;
                sm[r * 132 + hq * 8 + 2 * k + 1] = f.y;
            }
        }
        __syncthreads();
        for (int idx = tid; idx < 288; idx += 256) {
            int r = idx / 9, o = idx - r * 9;
            float s = headB[o];
            const float* hr = sm + r * 132;
#pragma unroll 8
            for (int jj = 0; jj < 128; jj++) s += hr[jj] * hw_s[jj * 9 + o];
            outPrev[(size_t)(hr0 + r) * 9 + o] = s;
        }
    }
}

__global__ __launch_bounds__(256, 2)
void lstm_single_kernel(const float* __restrict__ Aps, int kps,
                        const __half* __restrict__ Aha, int kha,
                        const __half* __restrict__ Ahb, int khb,
                        const uint32_t* __restrict__ Wp, const float* __restrict__ biasp,
                        const float* __restrict__ Cprev, float* __restrict__ Cout,
                        __half* __restrict__ Hout)
{
    extern __shared__ float sm[];
    uint32_t smb = smem_u32(sm);
    lstm_core(blockIdx.x, sm, smb, Aps, kps, Aha, kha, Ahb, khb, Wp, biasp,
              Cprev, Cout, Hout, nullptr, nullptr, nullptr, nullptr);
}

__global__ __launch_bounds__(256, 2)
void lstm_merged_kernel(const float* __restrict__ ps_s,
                        const __half* __restrict__ h1prev, __half* __restrict__ h1out,
                        const __half* __restrict__ h2old, int kh2, __half* __restrict__ h2out,
                        const uint32_t* __restrict__ W1, const float* __restrict__ b1,
                        const uint32_t* __restrict__ W2, const float* __restrict__ b2,
                        float* __restrict__ c1, const float* __restrict__ c2prev,
                        float* __restrict__ c2,
                        const __half* __restrict__ h2head, const float* __restrict__ headW,
                        const float* __restrict__ headB, float* __restrict__ outPrev)
{
    extern __shared__ float sm[];
    uint32_t smb = smem_u32(sm);
    if (blockIdx.x < 1024) {
        lstm_core(blockIdx.x, sm, smb, ps_s, 256, h1prev, 128, nullptr, 0,
                  W1, b1, c1, c1, h1out, h2head, headW, headB, outPrev);
    } else {
        lstm_core(blockIdx.x - 1024, sm, smb, nullptr, 0, h1prev, 128, h2old, kh2,
                  W2, b2, c2prev, c2, h2out, nullptr, nullptr, nullptr, nullptr);
    }
}

// ---------------- final head kernel: steps 15 and 16 (fp16 h2) ----------------
__global__ __launch_bounds__(256)
void head2_kernel(const __half* __restrict__ h2a, const __half* __restrict__ h2b,
                  const float* __restrict__ headW, const float* __restrict__ headB,
                  float* __restrict__ outA, float* __restrict__ outB)
{
    __shared__ float hs[64 * 132];
    __shared__ float hw[1152];
    const int t = threadIdx.x;
    const bool second = blockIdx.x >= 512;
    const __half* h2 = second ? h2b : h2a;
    float* outp = second ? outB : outA;
    const int r0 = (second ? (blockIdx.x - 512) : blockIdx.x) * 64;
    for (int idx = t; idx < 1152; idx += 256) {
        int j = idx / 9, o = idx - j * 9;
        hw[idx] = headW[o * 128 + j];
    }
#pragma unroll
    for (int it = 0; it < 4; it++) {
        int idx = t + it * 256;
        int r = idx >> 4, hq = idx & 15;
        uint4 v = *(const uint4*)(h2 + (size_t)(r0 + r) * 128 + hq * 8);
        const __half2* hp = (const __half2*)&v;
#pragma unroll
        for (int k = 0; k < 4; k++) {
            float2 f = __half22float2(hp[k]);
            hs[r * 132 + hq * 8 + 2 * k]     = f.x;
            hs[r * 132 + hq * 8 + 2 * k + 1] = f.y;
        }
    }
    __syncthreads();
    for (int idx = t; idx < 576; idx += 256) {
        int r = idx / 9, o = idx - r * 9;
        float s = headB[o];
        const float* hr = hs + r * 132;
#pragma unroll 8
        for (int jj = 0; jj < 128; jj++) s += hr[jj] * hw[jj * 9 + o];
        outp[(size_t)(r0 + r) * 9 + o] = s;
    }
}

// ---------------- launch ----------------
extern "C" void kernel_launch(void* const* d_in, const int* in_sizes, int n_in,
                              void* d_out, int out_size) {
    const float* x        = (const float*)d_in[0];
    const float* ps       = (const float*)d_in[1];
    const float* conv1_w  = (const float*)d_in[2];
    const float* conv1_b  = (const float*)d_in[3];
    const float* conv2_w  = (const float*)d_in[4];
    const float* conv2_b  = (const float*)d_in[5];
    const float* conv3_w  = (const float*)d_in[6];
    const float* conv3_b  = (const float*)d_in[7];
    const float* w_ih1    = (const float*)d_in[8];
    const float* w_hh1    = (const float*)d_in[9];
    const float* b_ih1    = (const float*)d_in[10];
    const float* b_hh1    = (const float*)d_in[11];
    const float* w_ih2    = (const float*)d_in[12];
    const float* w_hh2    = (const float*)d_in[13];
    const float* b_ih2    = (const float*)d_in[14];
    const float* b_hh2    = (const float*)d_in[15];
    const float* head_w   = (const float*)d_in[16];
    const float* head_b   = (const float*)d_in[17];
    float* out = (float*)d_out;

    cudaFuncSetAttribute(conv_kernel, cudaFuncAttributeMaxDynamicSharedMemorySize, CONV_SMEM_BYTES);
    cudaFuncSetAttribute(lstm_single_kernel, cudaFuncAttributeMaxDynamicSharedMemorySize, SMEM_LSTM_BYTES);
    cudaFuncSetAttribute(lstm_merged_kernel, cudaFuncAttributeMaxDynamicSharedMemorySize, SMEM_LSTM_BYTES);

    __half *feath, *h1h, *h2h;
    float *c1, *c2, *b1p, *b2p;
    uint32_t *W1h, *W2h;
    cudaGetSymbolAddress((void**)&feath, g_feath);
    cudaGetSymbolAddress((void**)&h1h, g_h1h);
    cudaGetSymbolAddress((void**)&h2h, g_h2h);
    cudaGetSymbolAddress((void**)&c1, g_c1);
    cudaGetSymbolAddress((void**)&c2, g_c2);
    cudaGetSymbolAddress((void**)&W1h, g_W1h);
    cudaGetSymbolAddress((void**)&W2h, g_W2h);
    cudaGetSymbolAddress((void**)&b1p, g_b1p);
    cudaGetSymbolAddress((void**)&b2p, g_b2p);

    const int prep_total = 12 * 8192 + 8 * 8192 + 1024 + 7168 + 32768;
    prep_kernel<<<(prep_total + 255) / 256, 256>>>(w_ih1, w_hh1, b_ih1, b_hh1,
                                                   w_ih2, w_hh2, b_ih2, b_hh2,
                                                   conv2_w, conv3_w);

    conv_kernel<<<Bn / 32, 256, CONV_SMEM_BYTES>>>(x, conv1_w, conv1_b, conv2_b, conv3_b);

    // L1_0: A = feat (fp16), cold state -> h1h[0], c1
    lstm_single_kernel<<<1024, 256, SMEM_LSTM_BYTES>>>(
        nullptr, 0, feath, 128, nullptr, 0, W1h, b1p, nullptr, c1, h1h);

    // merged steps: launch s = [L1_s | L2_{s-1}]
    for (int s = 1; s <= Tn; s++) {
        const float* A       = ps + (size_t)(s - 1) * Bn * 256;
        const __half* h1prev = h1h + (size_t)((s - 1) & 1) * BH;
        __half*       h1out  = h1h + (size_t)(s & 1) * BH;
        const __half* h2old  = (s >= 2) ? (h2h + (size_t)(s & 1) * BH) : nullptr;
        __half*       h2out  = h2h + (size_t)((s - 1) & 1) * BH;
        lstm_merged_kernel<<<2048, 256, SMEM_LSTM_BYTES>>>(
            A, h1prev, h1out, h2old, (s >= 2) ? 128 : 0, h2out,
            W1h, b1p, W2h, b2p,
            c1, (s >= 2) ? c2 : nullptr, c2,
            h2old, head_w, head_b,
            (s >= 2) ? (out + (size_t)(s - 2) * Bn * 9) : nullptr);
    }

    // L2_16: h1_16 = h1h[0], h2_15 = h2h[1] -> h2h[0]
    lstm_single_kernel<<<1024, 256, SMEM_LSTM_BYTES>>>(
        nullptr, 0, h1h, 128, h2h + BH, 128, W2h, b2p, c2, c2, h2h);

    // heads for steps 15 (h2h[1]) and 16 (h2h[0])
    head2_kernel<<<1024, 256>>>(h2h + BH, h2h, head_w, head_b,
                                out + (size_t)15 * Bn * 9, out + (size_t)16 * Bn * 9);
}

// round 15
// speedup vs baseline: 1.2647x; 1.0322x over previous
#include <cuda_runtime.h>
#include <cuda_fp16.h>
#include <math.h>
#include <stdint.h>

#define Bn 32768
#define Tn 16
#define BH (Bn * 128)

// ---------------- device scratch (R12 state types: fp32) ----------------
__device__ float    g_feat[BH];
__device__ float    g_h1[2 * BH];
__device__ float    g_h2[2 * BH];
__device__ float    g_c1[BH];
__device__ float    g_c2[BH];
__device__ __align__(16) uint32_t g_W1h[12 * 8192];
__device__ __align__(16) uint32_t g_W2h[8 * 8192];
__device__ __align__(16) uint32_t g_W2c[7168];
__device__ __align__(16) uint32_t g_W3c[32768];
__device__ float    g_b1p[512];   // gate-interleaved n' = 4j+gate
__device__ float    g_b2p[512];

// ---------------- helpers ----------------
__device__ __forceinline__ uint32_t smem_u32(const void* p) {
    uint32_t r;
    asm("{ .reg .u64 t; cvta.to.shared.u64 t, %1; cvt.u32.u64 %0, t; }" : "=r"(r) : "l"(p));
    return r;
}
#define CP16(dst, src) asm volatile("cp.async.cg.shared.global [%0], [%1], 16;" :: "r"(dst), "l"(src))
#define CP_COMMIT()    asm volatile("cp.async.commit_group;" ::: "memory")
#define CP_WAIT0()     asm volatile("cp.async.wait_group 0;" ::: "memory")
#define CP_WAIT1()     asm volatile("cp.async.wait_group 1;" ::: "memory")

#define MMA_F16(d, a, b0v, b1v) \
    asm volatile("mma.sync.aligned.m16n8k16.row.col.f32.f16.f16.f32 " \
        "{%0,%1,%2,%3}, {%4,%5,%6,%7}, {%8,%9}, {%0,%1,%2,%3};" \
        : "+f"((d)[0]), "+f"((d)[1]), "+f"((d)[2]), "+f"((d)[3]) \
        : "r"((a)[0]), "r"((a)[1]), "r"((a)[2]), "r"((a)[3]), "r"(b0v), "r"(b1v))

__device__ __forceinline__ uint32_t pack_h2(float lo, float hi) {
    __half2 h = __floats2half2_rn(lo, hi);
    uint32_t u;
    memcpy(&u, &h, 4);
    return u;
}
__device__ __forceinline__ float sigf(float x) { return __fdividef(1.0f, 1.0f + __expf(-x)); }
__device__ __forceinline__ float tanhx(float x) { return __fdividef(2.0f, 1.0f + __expf(-2.0f * x)) - 1.0f; }
__device__ __forceinline__ float eluf(float x) { return x > 0.0f ? x : expm1f(x); }

// ---------------- weight prep (identical to R12) ----------------
__global__ void prep_kernel(const float* __restrict__ w_ih1, const float* __restrict__ w_hh1,
                            const float* __restrict__ b_ih1, const float* __restrict__ b_hh1,
                            const float* __restrict__ w_ih2, const float* __restrict__ w_hh2,
                            const float* __restrict__ b_ih2, const float* __restrict__ b_hh2,
                            const float* __restrict__ w2c, const float* __restrict__ w3c) {
    int i = blockIdx.x * blockDim.x + threadIdx.x;
    const int total1 = 12 * 8192;
    const int total2 = 8 * 8192;
    const int base3  = total1 + total2 + 1024;
    if (i < total1 + total2) {
        int li = (i < total1) ? i : i - total1;
        int w    = li & 3;
        int lane = (li >> 2) & 31;
        int jp   = (li >> 7) & 3;
        int s    = (li >> 9) & 1;
        int wn2  = (li >> 10) & 3;
        int half = (li >> 12) & 1;
        int ch   = li >> 13;
        int g = lane >> 2, t4 = lane & 3;
        int j8 = jp * 2 + (w >> 1);
        int k  = ch * 32 + s * 16 + 8 * (w & 1) + 2 * t4;
        int np = half * 256 + wn2 * 64 + j8 * 8 + g;
        int j = np >> 2, gate = np & 3;
        int n = gate * 128 + j;
        float f0, f1;
        if (i < total1) {
            if (k < 256) { f0 = w_ih1[n * 256 + k];        f1 = w_ih1[n * 256 + k + 1]; }
            else         { f0 = w_hh1[n * 128 + k - 256];  f1 = w_hh1[n * 128 + k - 255]; }
            g_W1h[li] = pack_h2(f0, f1);
        } else {
            if (k < 128) { f0 = w_ih2[n * 128 + k];        f1 = w_ih2[n * 128 + k + 1]; }
            else         { f0 = w_hh2[n * 128 + k - 128];  f1 = w_hh2[n * 128 + k - 127]; }
            g_W2h[li] = pack_h2(f0, f1);
        }
    } else if (i < total1 + total2 + 512) {
        int np = i - total1 - total2;
        int j = np >> 2, gate = np & 3;
        int n = gate * 128 + j;
        g_b1p[np] = b_ih1[n] + b_hh1[n];
    } else if (i < base3) {
        int np = i - total1 - total2 - 512;
        int j = np >> 2, gate = np & 3;
        int n = gate * 128 + j;
        g_b2p[np] = b_ih2[n] + b_hh2[n];
    } else if (i < base3 + 7168) {
        int wi = i - base3;
        int w01  = wi & 1;
        int lane = (wi >> 1) & 31;
        int j8   = (wi >> 6) & 7;
        int sc   = wi >> 9;
        int g = lane >> 2, t4 = lane & 3;
        int n = j8 * 8 + g;
        int k0 = sc * 16 + 2 * t4 + 8 * w01;
        g_W2c[wi] = pack_h2(w2c[n * 224 + k0], w2c[n * 224 + k0 + 1]);
    } else if (i < base3 + 7168 + 32768) {
        int wi = i - base3 - 7168;
        int w01  = wi & 1;
        int lane = (wi >> 1) & 31;
        int j8   = (wi >> 6) & 15;
        int sc   = wi >> 10;
        int g = lane >> 2, t4 = lane & 3;
        int n = j8 * 8 + g;
        int k0 = sc * 16 + 2 * t4 + 8 * w01;
        float f0, f1;
        {
            int ci2 = k0 >> 3, p = k0 & 7;
            f0 = (p < 7) ? w3c[n * 448 + ci2 * 7 + p] : 0.0f;
        }
        {
            int k1 = k0 + 1;
            int ci2 = k1 >> 3, p = k1 & 7;
            f1 = (p < 7) ? w3c[n * 448 + ci2 * 7 + p] : 0.0f;
        }
        g_W3c[wi] = pack_h2(f0, f1);
    }
}

// ---------------- conv stack (exact R12, fp32 feat output) ----------------
#define CXS   0
#define CW2F  640
#define CB2S  7808
#define CB3S  7872
#define CA3W  8000
#define CW3R  16192
#define CY1H  20288
#define CA2W  26944
#define CW1S  55616
#define CB1S  55840
#define CONV_SMEM_WORDS 55872
#define CONV_SMEM_BYTES (CONV_SMEM_WORDS * 4)

__global__ __launch_bounds__(256, 1)
void conv_kernel(const float* __restrict__ x,
                 const float* __restrict__ w1, const float* __restrict__ b1,
                 const float* __restrict__ b2, const float* __restrict__ b3) {
    extern __shared__ float sm[];
    __half* smh = (__half*)sm;
    uint32_t* smw = (uint32_t*)sm;
    uint32_t smb = smem_u32(sm);

    const int t    = threadIdx.x;
    const int lane = t & 31;
    const int wid  = t >> 5;
    const int g    = lane >> 2;
    const int t4   = lane & 3;
    const int b0g  = blockIdx.x * 32;

#pragma unroll
    for (int it = 0; it < 7; it++) {
        int gi = it * 1024 + t * 4;
        CP16(smb + (CW2F + gi) * 4, g_W2c + gi);
    }
    CP_COMMIT();

    for (int idx = t; idx < 608; idx += 256) {
        int b = idx / 19, q = idx - b * 19;
        sm[CXS + b * 20 + q] = x[(size_t)(b0g + b) * 19 + q];
    }
    if (t < 224) sm[CW1S + t] = w1[t];
    if (t < 32)  sm[CB1S + t] = b1[t];
    if (t < 64)  sm[CB2S + t] = b2[t];
    if (t < 128) sm[CB3S + t] = b3[t];
    __syncthreads();

    for (int idx = t; idx < 13312; idx += 256) {
        int b = idx / 416;
        int rem = idx - b * 416;
        int ci = rem / 13, q = rem - ci * 13;
        float s = sm[CB1S + ci];
#pragma unroll
        for (int k = 0; k < 7; k++) s += sm[CXS + b * 20 + q + k] * sm[CW1S + ci * 7 + k];
        smh[CY1H * 2 + idx] = __float2half(eluf(s));
    }
    for (int idx = t; idx < 8192; idx += 256) sm[CA3W + idx] = 0.0f;
    __syncthreads();

    {
        const int r = t;
        const int b = r >> 3, p = r & 7;
        const int xr = 2 * (r & 7);
        if (p < 7) {
            const __half* y1r = smh + CY1H * 2 + b * 416 + p;
            int c = 0;
            for (int ci = 0; ci < 32; ci++) {
                const __half* yq = y1r + ci * 13;
#pragma unroll
                for (int k = 0; k < 7; k++, c++) {
                    int ch = c >> 5, hc = c & 31;
                    int phys = (hc >> 1) ^ xr;
                    smh[(CA2W + ch * 4096 + r * 16 + phys) * 2 + (hc & 1)] = yq[k];
                }
            }
        } else {
            const __half z = __float2half(0.0f);
            for (int c = 0; c < 224; c++) {
                int ch = c >> 5, hc = c & 31;
                int phys = (hc >> 1) ^ xr;
                smh[(CA2W + ch * 4096 + r * 16 + phys) * 2 + (hc & 1)] = z;
            }
        }
    }
    CP_WAIT0();
    __syncthreads();

    auto issueW3 = [&](int i) {
        const uint32_t* src = g_W3c + i * 2048;
        uint32_t dst = smb + (CW3R + (i & 1) * 2048) * 4;
#pragma unroll
        for (int it = 0; it < 2; it++) {
            int gi = it * 1024 + t * 4;
            CP16(dst + gi * 4, src + gi);
        }
        CP_COMMIT();
    };
    issueW3(0);
    issueW3(1);

    const int wm2 = wid & 3;
    const int wn  = wid >> 2;
    float acc2[4][4][4];
#pragma unroll
    for (int mt = 0; mt < 4; mt++)
#pragma unroll
        for (int jp = 0; jp < 4; jp++)
#pragma unroll
            for (int q = 0; q < 4; q++) acc2[mt][jp][q] = 0.0f;

    for (int ch = 0; ch < 7; ch++) {
        const uint32_t* Ab = smw + CA2W + ch * 4096;
#pragma unroll
        for (int s = 0; s < 2; s++) {
            uint2 bf[4];
#pragma unroll
            for (int jp = 0; jp < 4; jp++) {
                int j8 = wn * 4 + jp;
                bf[jp] = *(const uint2*)(smw + CW2F + ((ch * 2 + s) * 8 + j8) * 64 + lane * 2);
            }
            int w0  = (s * 8 + t4) ^ (2 * g);
            int w1i = (s * 8 + 4 + t4) ^ (2 * g);
#pragma unroll
            for (int mt = 0; mt < 4; mt++) {
                int r0 = wm2 * 64 + mt * 16;
                uint32_t a[4];
                a[0] = Ab[(r0 + g) * 16 + w0];
                a[1] = Ab[(r0 + g + 8) * 16 + w0];
                a[2] = Ab[(r0 + g) * 16 + w1i];
                a[3] = Ab[(r0 + g + 8) * 16 + w1i];
#pragma unroll
                for (int jp = 0; jp < 4; jp++)
                    MMA_F16(acc2[mt][jp], a, bf[jp].x, bf[jp].y);
            }
        }
    }

#pragma unroll
    for (int mt = 0; mt < 4; mt++) {
#pragma unroll
        for (int q = 0; q < 4; q++) {
            int r = wm2 * 64 + mt * 16 + g + ((q >> 1) << 3);
            int p = r & 7;
            if (p == 7) continue;
            int b = r >> 3;
            int xr = 2 * (b & 7);
#pragma unroll
            for (int jp = 0; jp < 4; jp++) {
                int n = wn * 32 + jp * 8 + 2 * t4 + (q & 1);
                float v = eluf(acc2[mt][jp][q] + sm[CB2S + n]);
                int c3 = n * 8 + p;
                int ch3 = c3 >> 5, hc = c3 & 31;
                int phys = (hc >> 1) ^ xr;
                smh[(CA3W + ch3 * 512 + b * 16 + phys) * 2 + (hc & 1)] = __float2half(v);
            }
        }
    }
    __syncthreads();

    const int wm3 = wid & 1;
    const int wn3 = wid >> 1;
    float acc3[4][4];
#pragma unroll
    for (int jp = 0; jp < 4; jp++)
#pragma unroll
        for (int q = 0; q < 4; q++) acc3[jp][q] = 0.0f;

    for (int i = 0; i < 16; i++) {
        if (i < 14) { CP_WAIT1(); } else { CP_WAIT0(); }
        __syncthreads();
        const uint32_t* Br = smw + CW3R + (i & 1) * 2048;
        const uint32_t* Ab = smw + CA3W + i * 512;
#pragma unroll
        for (int s = 0; s < 2; s++) {
            int w0  = (s * 8 + t4) ^ (2 * g);
            int w1i = (s * 8 + 4 + t4) ^ (2 * g);
            int r0 = wm3 * 16;
            uint32_t a[4];
            a[0] = Ab[(r0 + g) * 16 + w0];
            a[1] = Ab[(r0 + g + 8) * 16 + w0];
            a[2] = Ab[(r0 + g) * 16 + w1i];
            a[3] = Ab[(r0 + g + 8) * 16 + w1i];
#pragma unroll
            for (int jp = 0; jp < 4; jp++) {
                int j8 = wn3 * 4 + jp;
                uint2 bf = *(const uint2*)(Br + (s * 16 + j8) * 64 + lane * 2);
                MMA_F16(acc3[jp], a, bf.x, bf.y);
            }
        }
        __syncthreads();
        if (i + 2 < 16) issueW3(i + 2);
    }

#pragma unroll
    for (int jp = 0; jp < 4; jp++) {
#pragma unroll
        for (int q = 0; q < 4; q++) {
            int r = wm3 * 16 + g + ((q >> 1) << 3);
            int col = wn3 * 32 + jp * 8 + 2 * t4 + (q & 1);
            g_feat[(size_t)(b0g + r) * 128 + col] = eluf(acc3[jp][q] + sm[CB3S + col]);
        }
    }
}

// ---------------- fp16 LSTM-cell GEMM core (quarter-N CTA, 3 CTA/SM) ----------------
// smem words: B ring 3x2048 @0, A ring 3x1024 @6144, bias(128) @9216, hw @9344.
// Total 10496 words = 41984 B. Staging [64][132]=8448 reuses B+A rings.
#define AOFF  6144
#define BIASO 9216
#define HWO   9344
#define SMEM_LSTM_WORDS 10496
#define SMEM_LSTM_BYTES (SMEM_LSTM_WORDS * 4)

__device__ __forceinline__ void lstm_core(
    int blk, float* sm, uint32_t smb,
    const float* __restrict__ A0, int lda0, int k0len,
    const float* __restrict__ A1, int k1len,
    const uint32_t* __restrict__ Wp, const float* __restrict__ biasp,
    const float* __restrict__ Cprev, float* __restrict__ Hout, float* __restrict__ Cout,
    const float* __restrict__ h2head, const float* __restrict__ headW,
    const float* __restrict__ headB, float* __restrict__ outPrev)
{
    uint32_t* smw = (uint32_t*)sm;
    float* bias_s = sm + BIASO;
    float* hw_s   = sm + HWO;

    const int tid  = threadIdx.x;
    const int wid  = tid >> 5;
    const int lane = tid & 31;
    const int g    = lane >> 2;
    const int t4   = lane & 3;
    const int wm   = wid & 1;
    const int wn4  = wid >> 1;           // 0..3: 32 N' cols each
    const int wn2sel = wn4 >> 1;
    const int jph  = wn4 & 1;
    const int quarter = blk & 3;
    const int row0 = (blk >> 2) * 64;
    const int ar   = tid >> 3;
    const int aq   = tid & 7;

    if (tid < 128) bias_s[tid] = biasp[quarter * 128 + tid];
    if (h2head) {
        for (int idx = tid; idx < 1152; idx += 256) {
            int j = idx / 9, o = idx - j * 9;
            hw_s[idx] = headW[o * 128 + j];
        }
    }
    __syncthreads();

    float acc[2][4][4];
#pragma unroll
    for (int mt = 0; mt < 2; mt++)
#pragma unroll
        for (int jc = 0; jc < 4; jc++)
#pragma unroll
            for (int q = 0; q < 4; q++) acc[mt][jc][q] = 0.0f;

    const int nch = (k0len + k1len) >> 5;
    const int awsw = (2 * aq) ^ (2 * (ar & 7));

    // rings
    const uint32_t* aw0 = smw + AOFF;
    const uint32_t* aw1 = aw0 + 1024;
    const uint32_t* aw2 = aw1 + 1024;
    const uint4* bq0 = (const uint4*)(smw) + wn2sel * 256;
    const uint4* bq1 = (const uint4*)(smw + 2048) + wn2sel * 256;
    const uint4* bq2 = (const uint4*)(smw + 4096) + wn2sel * 256;
    uint32_t* sp0 = smw + AOFF + ar * 16 + awsw;
    uint32_t* sp1 = sp0 + 1024;
    uint32_t* sp2 = sp1 + 1024;
    uint32_t bb0 = smb + (uint32_t)tid * 16u;
    uint32_t bb1 = bb0 + 8192u;
    uint32_t bb2 = bb1 + 8192u;

    const uint32_t* wbase = Wp + (size_t)(quarter >> 1) * 4096 + (size_t)(quarter & 1) * 2048;

    auto ldgA = [&](int i, float4 v[2]) {
        int kb = i << 5;
        const float* src; int ld; int col;
        if (kb < k0len) { src = A0; ld = lda0; col = kb; }
        else            { src = A1; ld = 128;  col = kb - k0len; }
        v[0] = *(const float4*)(src + (size_t)(row0 + ar) * ld + col + aq * 4);
        v[1] = *(const float4*)(src + (size_t)(row0 + ar + 32) * ld + col + aq * 4);
    };
    auto stsA = [&](uint32_t* p, const float4 v[2]) {
        p[0]   = pack_h2(v[0].x, v[0].y);
        p[1]   = pack_h2(v[0].z, v[0].w);
        p[512] = pack_h2(v[1].x, v[1].y);
        p[513] = pack_h2(v[1].z, v[1].w);
    };
    auto issueB = [&](int i, uint32_t bb) {
        const uint32_t* wsrc = wbase + (size_t)i * 8192;
#pragma unroll
        for (int it = 0; it < 2; it++) {
            CP16(bb + (uint32_t)it * 4096u, wsrc + (size_t)(it * 256 + tid) * 4);
        }
        CP_COMMIT();
    };

    // prologue
    float4 hold[2];
    {
        float4 a0v[2];
        ldgA(0, a0v);
        stsA(sp0, a0v);
        issueB(0, bb0);
        if (nch > 1) { ldgA(1, hold); issueB(1, bb1); }
    }

    const int xg = 2 * g;
    const int r0a = wm * 32 + g;
    for (int i = 0; i < nch; i++) {
        if (i == nch - 1) { CP_WAIT0(); } else { CP_WAIT1(); }
        __syncthreads();
        if (i + 1 < nch) stsA(sp1, hold);
        if (i + 2 < nch) { ldgA(i + 2, hold); issueB(i + 2, bb2); }

        const uint32_t* Aw = aw0;
        const uint4*    Bq = bq0;

#pragma unroll
        for (int s = 0; s < 2; s++) {
            uint4 bv[2];
#pragma unroll
            for (int jj = 0; jj < 2; jj++) bv[jj] = Bq[s * 128 + (jph * 2 + jj) * 32 + lane];
            uint32_t a[2][4];
#pragma unroll
            for (int mt = 0; mt < 2; mt++) {
                int r0 = r0a + mt * 16;
                int w0 = (s * 8 + t4) ^ xg;
                int w1 = (s * 8 + 4 + t4) ^ xg;
                a[mt][0] = Aw[r0 * 16 + w0];
                a[mt][1] = Aw[(r0 + 8) * 16 + w0];
                a[mt][2] = Aw[r0 * 16 + w1];
                a[mt][3] = Aw[(r0 + 8) * 16 + w1];
            }
#pragma unroll
            for (int jj = 0; jj < 2; jj++) {
                MMA_F16(acc[0][2 * jj],     a[0], bv[jj].x, bv[jj].y);
                MMA_F16(acc[1][2 * jj],     a[1], bv[jj].x, bv[jj].y);
                MMA_F16(acc[0][2 * jj + 1], a[0], bv[jj].z, bv[jj].w);
                MMA_F16(acc[1][2 * jj + 1], a[1], bv[jj].z, bv[jj].w);
            }
        }
        { const uint32_t* t0 = aw0; aw0 = aw1; aw1 = aw2; aw2 = t0; }
        { const uint4* t0 = bq0; bq0 = bq1; bq1 = bq2; bq2 = t0; }
        { uint32_t* t0 = sp0; sp0 = sp1; sp1 = sp2; sp2 = t0; }
        { uint32_t t0 = bb0; bb0 = bb1; bb1 = bb2; bb2 = t0; }
    }
    __syncthreads();

    // stage gates to [64][132]
#pragma unroll
    for (int mt = 0; mt < 2; mt++) {
        int row = wm * 32 + mt * 16 + g;
#pragma unroll
        for (int jc = 0; jc < 4; jc++) {
            int col = wn4 * 32 + jc * 8 + 2 * t4;
            sm[row * 132 + col]           = acc[mt][jc][0];
            sm[row * 132 + col + 1]       = acc[mt][jc][1];
            sm[(row + 8) * 132 + col]     = acc[mt][jc][2];
            sm[(row + 8) * 132 + col + 1] = acc[mt][jc][3];
        }
    }
    __syncthreads();

    // cell epilogue: thread jl = tid&31 (local j), rg = tid>>5 (8 rows each)
    {
        const int jl = tid & 31;
        const int rg = tid >> 5;
        const int col = quarter * 32 + jl;
        const float4 bb = *(const float4*)(bias_s + 4 * jl);
#pragma unroll
        for (int rr = 0; rr < 8; rr++) {
            int r = rg * 8 + rr;
            int row = row0 + r;
            float4 gv = *(const float4*)(sm + r * 132 + 4 * jl);
            float gi = gv.x + bb.x;
            float gf = gv.y + bb.y;
            float gg = gv.z + bb.z;
            float go = gv.w + bb.w;
            float cp = Cprev ? Cprev[(size_t)row * 128 + col] : 0.0f;
            float c  = sigf(gf) * cp + sigf(gi) * tanhx(gg);
            float h  = sigf(go) * tanhx(c);
            Cout[(size_t)row * 128 + col] = c;
            Hout[(size_t)row * 128 + col] = h;
        }
    }

    // head for an older step's h2 (16 rows per quarter CTA)
    if (h2head) {
        __syncthreads();
        const int hr0 = row0 + quarter * 16;
#pragma unroll
        for (int it = 0; it < 8; it++) {
            int idx = tid + it * 256;
            int r = idx >> 7, cq = idx & 127;
            sm[r * 132 + cq] = h2head[(size_t)(hr0 + r) * 128 + cq];
        }
        __syncthreads();
        for (int idx = tid; idx < 144; idx += 256) {
            int r = idx / 9, o = idx - r * 9;
            float s = headB[o];
            const float* hr = sm + r * 132;
#pragma unroll 8
            for (int jj = 0; jj < 128; jj++) s += hr[jj] * hw_s[jj * 9 + o];
            outPrev[(size_t)(hr0 + r) * 9 + o] = s;
        }
    }
}

__global__ __launch_bounds__(256, 3)
void lstm_single_kernel(const float* __restrict__ A0, int lda0, int k0len,
                        const float* __restrict__ A1, int k1len,
                        const uint32_t* __restrict__ Wp, const float* __restrict__ biasp,
                        const float* __restrict__ Cprev,
                        float* __restrict__ Hout, float* __restrict__ Cout)
{
    extern __shared__ float sm[];
    uint32_t smb = smem_u32(sm);
    lstm_core(blockIdx.x, sm, smb, A0, lda0, k0len, A1, k1len, Wp, biasp,
              Cprev, Hout, Cout, nullptr, nullptr, nullptr, nullptr);
}

__global__ __launch_bounds__(256, 3)
void lstm_merged_kernel(const float* __restrict__ a0_1, const float* __restrict__ a1_1,
                        const uint32_t* __restrict__ W_1, const float* __restrict__ b_1,
                        const float* __restrict__ cp_1,
                        float* __restrict__ ho_1, float* __restrict__ co_1,
                        const float* __restrict__ h2head, const float* __restrict__ headW,
                        const float* __restrict__ headB, float* __restrict__ outPrev,
                        const float* __restrict__ a0_2, const float* __restrict__ a1_2, int k1_2,
                        const uint32_t* __restrict__ W_2, const float* __restrict__ b_2,
                        const float* __restrict__ cp_2,
                        float* __restrict__ ho_2, float* __restrict__ co_2)
{
    extern __shared__ float sm[];
    uint32_t smb = smem_u32(sm);
    if (blockIdx.x < 2048) {
        lstm_core(blockIdx.x, sm, smb, a0_1, 256, 256, a1_1, 128, W_1, b_1,
                  cp_1, ho_1, co_1, h2head, headW, headB, outPrev);
    } else {
        lstm_core(blockIdx.x - 2048, sm, smb, a0_2, 128, 128, a1_2, k1_2, W_2, b_2,
                  cp_2, ho_2, co_2, nullptr, nullptr, nullptr, nullptr);
    }
}

// ---------------- final head kernel: steps 15 and 16 (fp32 h2, exact R12) ----------------
__global__ __launch_bounds__(256)
void head2_kernel(const float* __restrict__ h2a, const float* __restrict__ h2b,
                  const float* __restrict__ headW, const float* __restrict__ headB,
                  float* __restrict__ outA, float* __restrict__ outB)
{
    __shared__ float hs[64 * 132];
    __shared__ float hw[1152];
    const int t = threadIdx.x;
    const bool second = blockIdx.x >= 512;
    const float* h2 = second ? h2b : h2a;
    float* outp = second ? outB : outA;
    const int r0 = (second ? (blockIdx.x - 512) : blockIdx.x) * 64;
    for (int idx = t; idx < 1152; idx += 256) {
        int j = idx / 9, o = idx - j * 9;
        hw[idx] = headW[o * 128 + j];
    }
#pragma unroll
    for (int it = 0; it < 8; it++) {
        int idx = t + it * 256;
        int r = idx >> 5, cq = idx & 31;
        float4 v = *(const float4*)(h2 + (size_t)(r0 + r) * 128 + cq * 4);
        hs[r * 132 + cq * 4]     = v.x;
        hs[r * 132 + cq * 4 + 1] = v.y;
        hs[r * 132 + cq * 4 + 2] = v.z;
        hs[r * 132 + cq * 4 + 3] = v.w;
    }
    __syncthreads();
    for (int idx = t; idx < 576; idx += 256) {
        int r = idx / 9, o = idx - r * 9;
        float s = headB[o];
        const float* hr = hs + r * 132;
#pragma unroll 8
        for (int jj = 0; jj < 128; jj++) s += hr[jj] * hw[jj * 9 + o];
        outp[(size_t)(r0 + r) * 9 + o] = s;
    }
}

// ---------------- launch ----------------
extern "C" void kernel_launch(void* const* d_in, const int* in_sizes, int n_in,
                              void* d_out, int out_size) {
    const float* x        = (const float*)d_in[0];
    const float* ps       = (const float*)d_in[1];
    const float* conv1_w  = (const float*)d_in[2];
    const float* conv1_b  = (const float*)d_in[3];
    const float* conv2_w  = (const float*)d_in[4];
    const float* conv2_b  = (const float*)d_in[5];
    const float* conv3_w  = (const float*)d_in[6];
    const float* conv3_b  = (const float*)d_in[7];
    const float* w_ih1    = (const float*)d_in[8];
    const float* w_hh1    = (const float*)d_in[9];
    const float* b_ih1    = (const float*)d_in[10];
    const float* b_hh1    = (const float*)d_in[11];
    const float* w_ih2    = (const float*)d_in[12];
    const float* w_hh2    = (const float*)d_in[13];
    const float* b_ih2    = (const float*)d_in[14];
    const float* b_hh2    = (const float*)d_in[15];
    const float* head_w   = (const float*)d_in[16];
    const float* head_b   = (const float*)d_in[17];
    float* out = (float*)d_out;

    cudaFuncSetAttribute(conv_kernel, cudaFuncAttributeMaxDynamicSharedMemorySize, CONV_SMEM_BYTES);
    cudaFuncSetAttribute(lstm_single_kernel, cudaFuncAttributeMaxDynamicSharedMemorySize, SMEM_LSTM_BYTES);
    cudaFuncSetAttribute(lstm_merged_kernel, cudaFuncAttributeMaxDynamicSharedMemorySize, SMEM_LSTM_BYTES);

    float *feat, *h1, *h2, *c1, *c2, *b1p, *b2p;
    uint32_t *W1h, *W2h;
    cudaGetSymbolAddress((void**)&feat, g_feat);
    cudaGetSymbolAddress((void**)&h1, g_h1);
    cudaGetSymbolAddress((void**)&h2, g_h2);
    cudaGetSymbolAddress((void**)&c1, g_c1);
    cudaGetSymbolAddress((void**)&c2, g_c2);
    cudaGetSymbolAddress((void**)&W1h, g_W1h);
    cudaGetSymbolAddress((void**)&W2h, g_W2h);
    cudaGetSymbolAddress((void**)&b1p, g_b1p);
    cudaGetSymbolAddress((void**)&b2p, g_b2p);

    const int prep_total = 12 * 8192 + 8 * 8192 + 1024 + 7168 + 32768;
    prep_kernel<<<(prep_total + 255) / 256, 256>>>(w_ih1, w_hh1, b_ih1, b_hh1,
                                                   w_ih2, w_hh2, b_ih2, b_hh2,
                                                   conv2_w, conv3_w);

    conv_kernel<<<Bn / 32, 256, CONV_SMEM_BYTES>>>(x, conv1_w, conv1_b, conv2_b, conv3_b);

    // L1_0: writes h1[0], c1
    lstm_single_kernel<<<2048, 256, SMEM_LSTM_BYTES>>>(
        feat, 128, 128, nullptr, 0, W1h, b1p, nullptr, h1, c1);

    // merged steps: launch s = [L1_s | L2_{s-1}], 4096 quarter-CTAs
    for (int s = 1; s <= Tn; s++) {
        const float* A      = ps + (size_t)(s - 1) * Bn * 256;
        const float* h1prev = h1 + (size_t)((s - 1) & 1) * BH;
        float*       h1out  = h1 + (size_t)(s & 1) * BH;
        const float* h2old  = h2 + (size_t)(s & 1) * BH;        // h2_{s-2}, valid s>=2
        float*       h2out  = h2 + (size_t)((s - 1) & 1) * BH;  // h2_{s-1}
        lstm_merged_kernel<<<4096, 256, SMEM_LSTM_BYTES>>>(
            A, h1prev, W1h, b1p, c1, h1out, c1,
            (s >= 2) ? h2old : nullptr, head_w, head_b,
            (s >= 2) ? (out + (size_t)(s - 2) * Bn * 9) : nullptr,
            h1prev, (s >= 2) ? h2old : nullptr, (s >= 2) ? 128 : 0,
            W2h, b2p, (s >= 2) ? c2 : nullptr, h2out, c2);
    }

    // L2_16: h1_16 = h1[0], h2_15 = h2[1] -> h2[0]
    lstm_single_kernel<<<2048, 256, SMEM_LSTM_BYTES>>>(
        h1, 128, 128, h2 + BH, 128, W2h, b2p, c2, h2, c2);

    // heads for steps 15 and 16
    head2_kernel<<<1024, 256>>>(h2 + BH, h2, head_w, head_b,
                                out + (size_t)15 * Bn * 9, out + (size_t)16 * Bn * 9);
}

// round 16
// speedup vs baseline: 1.3572x; 1.0731x over previous
#include <cuda_runtime.h>
#include <cuda_fp16.h>
#include <math.h>
#include <stdint.h>

#define Bn 32768
#define Tn 16
#define BH (Bn * 128)

// ---------------- device scratch (R12 state: fp32) ----------------
__device__ float    g_feat[BH];
__device__ float    g_h1[2 * BH];
__device__ float    g_h2[2 * BH];
__device__ float    g_c1[BH];
__device__ float    g_c2[BH];
__device__ __align__(16) uint32_t g_W1h[12 * 8192];
__device__ __align__(16) uint32_t g_W2h[8 * 8192];
__device__ __align__(16) uint32_t g_W2c[7168];
__device__ __align__(16) uint32_t g_W3c[32768];
__device__ float    g_b1p[512];   // gate-interleaved n' = 4j+gate
__device__ float    g_b2p[512];

// ---------------- helpers ----------------
__device__ __forceinline__ uint32_t smem_u32(const void* p) {
    uint32_t r;
    asm("{ .reg .u64 t; cvta.to.shared.u64 t, %1; cvt.u32.u64 %0, t; }" : "=r"(r) : "l"(p));
    return r;
}
#define CP16(dst, src) asm volatile("cp.async.cg.shared.global [%0], [%1], 16;" :: "r"(dst), "l"(src))
#define CP_COMMIT()    asm volatile("cp.async.commit_group;" ::: "memory")
#define CP_WAIT0()     asm volatile("cp.async.wait_group 0;" ::: "memory")
#define CP_WAIT1()     asm volatile("cp.async.wait_group 1;" ::: "memory")

#define MMA_F16(d, a, b0v, b1v) \
    asm volatile("mma.sync.aligned.m16n8k16.row.col.f32.f16.f16.f32 " \
        "{%0,%1,%2,%3}, {%4,%5,%6,%7}, {%8,%9}, {%0,%1,%2,%3};" \
        : "+f"((d)[0]), "+f"((d)[1]), "+f"((d)[2]), "+f"((d)[3]) \
        : "r"((a)[0]), "r"((a)[1]), "r"((a)[2]), "r"((a)[3]), "r"(b0v), "r"(b1v))

__device__ __forceinline__ uint32_t pack_h2(float lo, float hi) {
    __half2 h = __floats2half2_rn(lo, hi);
    uint32_t u;
    memcpy(&u, &h, 4);
    return u;
}
__device__ __forceinline__ float sigf(float x) { return __fdividef(1.0f, 1.0f + __expf(-x)); }
__device__ __forceinline__ float tanhx(float x) { return __fdividef(2.0f, 1.0f + __expf(-2.0f * x)) - 1.0f; }
__device__ __forceinline__ float eluf(float x) { return x > 0.0f ? x : expm1f(x); }

// ---------------- weight prep (identical to R12) ----------------
__global__ void prep_kernel(const float* __restrict__ w_ih1, const float* __restrict__ w_hh1,
                            const float* __restrict__ b_ih1, const float* __restrict__ b_hh1,
                            const float* __restrict__ w_ih2, const float* __restrict__ w_hh2,
                            const float* __restrict__ b_ih2, const float* __restrict__ b_hh2,
                            const float* __restrict__ w2c, const float* __restrict__ w3c) {
    int i = blockIdx.x * blockDim.x + threadIdx.x;
    const int total1 = 12 * 8192;
    const int total2 = 8 * 8192;
    const int base3  = total1 + total2 + 1024;
    if (i < total1 + total2) {
        int li = (i < total1) ? i : i - total1;
        int w    = li & 3;
        int lane = (li >> 2) & 31;
        int jp   = (li >> 7) & 3;
        int s    = (li >> 9) & 1;
        int wn2  = (li >> 10) & 3;
        int half = (li >> 12) & 1;
        int ch   = li >> 13;
        int g = lane >> 2, t4 = lane & 3;
        int j8 = jp * 2 + (w >> 1);
        int k  = ch * 32 + s * 16 + 8 * (w & 1) + 2 * t4;
        int np = half * 256 + wn2 * 64 + j8 * 8 + g;
        int j = np >> 2, gate = np & 3;
        int n = gate * 128 + j;
        float f0, f1;
        if (i < total1) {
            if (k < 256) { f0 = w_ih1[n * 256 + k];        f1 = w_ih1[n * 256 + k + 1]; }
            else         { f0 = w_hh1[n * 128 + k - 256];  f1 = w_hh1[n * 128 + k - 255]; }
            g_W1h[li] = pack_h2(f0, f1);
        } else {
            if (k < 128) { f0 = w_ih2[n * 128 + k];        f1 = w_ih2[n * 128 + k + 1]; }
            else         { f0 = w_hh2[n * 128 + k - 128];  f1 = w_hh2[n * 128 + k - 127]; }
            g_W2h[li] = pack_h2(f0, f1);
        }
    } else if (i < total1 + total2 + 512) {
        int np = i - total1 - total2;
        int j = np >> 2, gate = np & 3;
        int n = gate * 128 + j;
        g_b1p[np] = b_ih1[n] + b_hh1[n];
    } else if (i < base3) {
        int np = i - total1 - total2 - 512;
        int j = np >> 2, gate = np & 3;
        int n = gate * 128 + j;
        g_b2p[np] = b_ih2[n] + b_hh2[n];
    } else if (i < base3 + 7168) {
        int wi = i - base3;
        int w01  = wi & 1;
        int lane = (wi >> 1) & 31;
        int j8   = (wi >> 6) & 7;
        int sc   = wi >> 9;
        int g = lane >> 2, t4 = lane & 3;
        int n = j8 * 8 + g;
        int k0 = sc * 16 + 2 * t4 + 8 * w01;
        g_W2c[wi] = pack_h2(w2c[n * 224 + k0], w2c[n * 224 + k0 + 1]);
    } else if (i < base3 + 7168 + 32768) {
        int wi = i - base3 - 7168;
        int w01  = wi & 1;
        int lane = (wi >> 1) & 31;
        int j8   = (wi >> 6) & 15;
        int sc   = wi >> 10;
        int g = lane >> 2, t4 = lane & 3;
        int n = j8 * 8 + g;
        int k0 = sc * 16 + 2 * t4 + 8 * w01;
        float f0, f1;
        {
            int ci2 = k0 >> 3, p = k0 & 7;
            f0 = (p < 7) ? w3c[n * 448 + ci2 * 7 + p] : 0.0f;
        }
        {
            int k1 = k0 + 1;
            int ci2 = k1 >> 3, p = k1 & 7;
            f1 = (p < 7) ? w3c[n * 448 + ci2 * 7 + p] : 0.0f;
        }
        g_W3c[wi] = pack_h2(f0, f1);
    }
}

// ---------------- conv stack (exact R12) ----------------
#define CXS   0
#define CW2F  640
#define CB2S  7808
#define CB3S  7872
#define CA3W  8000
#define CW3R  16192
#define CY1H  20288
#define CA2W  26944
#define CW1S  55616
#define CB1S  55840
#define CONV_SMEM_WORDS 55872
#define CONV_SMEM_BYTES (CONV_SMEM_WORDS * 4)

__global__ __launch_bounds__(256, 1)
void conv_kernel(const float* __restrict__ x,
                 const float* __restrict__ w1, const float* __restrict__ b1,
                 const float* __restrict__ b2, const float* __restrict__ b3) {
    extern __shared__ float sm[];
    __half* smh = (__half*)sm;
    uint32_t* smw = (uint32_t*)sm;
    uint32_t smb = smem_u32(sm);

    const int t    = threadIdx.x;
    const int lane = t & 31;
    const int wid  = t >> 5;
    const int g    = lane >> 2;
    const int t4   = lane & 3;
    const int b0g  = blockIdx.x * 32;

#pragma unroll
    for (int it = 0; it < 7; it++) {
        int gi = it * 1024 + t * 4;
        CP16(smb + (CW2F + gi) * 4, g_W2c + gi);
    }
    CP_COMMIT();

    for (int idx = t; idx < 608; idx += 256) {
        int b = idx / 19, q = idx - b * 19;
        sm[CXS + b * 20 + q] = x[(size_t)(b0g + b) * 19 + q];
    }
    if (t < 224) sm[CW1S + t] = w1[t];
    if (t < 32)  sm[CB1S + t] = b1[t];
    if (t < 64)  sm[CB2S + t] = b2[t];
    if (t < 128) sm[CB3S + t] = b3[t];
    __syncthreads();

    for (int idx = t; idx < 13312; idx += 256) {
        int b = idx / 416;
        int rem = idx - b * 416;
        int ci = rem / 13, q = rem - ci * 13;
        float s = sm[CB1S + ci];
#pragma unroll
        for (int k = 0; k < 7; k++) s += sm[CXS + b * 20 + q + k] * sm[CW1S + ci * 7 + k];
        smh[CY1H * 2 + idx] = __float2half(eluf(s));
    }
    for (int idx = t; idx < 8192; idx += 256) sm[CA3W + idx] = 0.0f;
    __syncthreads();

    {
        const int r = t;
        const int b = r >> 3, p = r & 7;
        const int xr = 2 * (r & 7);
        if (p < 7) {
            const __half* y1r = smh + CY1H * 2 + b * 416 + p;
            int c = 0;
            for (int ci = 0; ci < 32; ci++) {
                const __half* yq = y1r + ci * 13;
#pragma unroll
                for (int k = 0; k < 7; k++, c++) {
                    int ch = c >> 5, hc = c & 31;
                    int phys = (hc >> 1) ^ xr;
                    smh[(CA2W + ch * 4096 + r * 16 + phys) * 2 + (hc & 1)] = yq[k];
                }
            }
        } else {
            const __half z = __float2half(0.0f);
            for (int c = 0; c < 224; c++) {
                int ch = c >> 5, hc = c & 31;
                int phys = (hc >> 1) ^ xr;
                smh[(CA2W + ch * 4096 + r * 16 + phys) * 2 + (hc & 1)] = z;
            }
        }
    }
    CP_WAIT0();
    __syncthreads();

    auto issueW3 = [&](int i) {
        const uint32_t* src = g_W3c + i * 2048;
        uint32_t dst = smb + (CW3R + (i & 1) * 2048) * 4;
#pragma unroll
        for (int it = 0; it < 2; it++) {
            int gi = it * 1024 + t * 4;
            CP16(dst + gi * 4, src + gi);
        }
        CP_COMMIT();
    };
    issueW3(0);
    issueW3(1);

    const int wm2 = wid & 3;
    const int wn  = wid >> 2;
    float acc2[4][4][4];
#pragma unroll
    for (int mt = 0; mt < 4; mt++)
#pragma unroll
        for (int jp = 0; jp < 4; jp++)
#pragma unroll
            for (int q = 0; q < 4; q++) acc2[mt][jp][q] = 0.0f;

    for (int ch = 0; ch < 7; ch++) {
        const uint32_t* Ab = smw + CA2W + ch * 4096;
#pragma unroll
        for (int s = 0; s < 2; s++) {
            uint2 bf[4];
#pragma unroll
            for (int jp = 0; jp < 4; jp++) {
                int j8 = wn * 4 + jp;
                bf[jp] = *(const uint2*)(smw + CW2F + ((ch * 2 + s) * 8 + j8) * 64 + lane * 2);
            }
            int w0  = (s * 8 + t4) ^ (2 * g);
            int w1i = (s * 8 + 4 + t4) ^ (2 * g);
#pragma unroll
            for (int mt = 0; mt < 4; mt++) {
                int r0 = wm2 * 64 + mt * 16;
                uint32_t a[4];
                a[0] = Ab[(r0 + g) * 16 + w0];
                a[1] = Ab[(r0 + g + 8) * 16 + w0];
                a[2] = Ab[(r0 + g) * 16 + w1i];
                a[3] = Ab[(r0 + g + 8) * 16 + w1i];
#pragma unroll
                for (int jp = 0; jp < 4; jp++)
                    MMA_F16(acc2[mt][jp], a, bf[jp].x, bf[jp].y);
            }
        }
    }

#pragma unroll
    for (int mt = 0; mt < 4; mt++) {
#pragma unroll
        for (int q = 0; q < 4; q++) {
            int r = wm2 * 64 + mt * 16 + g + ((q >> 1) << 3);
            int p = r & 7;
            if (p == 7) continue;
            int b = r >> 3;
            int xr = 2 * (b & 7);
#pragma unroll
            for (int jp = 0; jp < 4; jp++) {
                int n = wn * 32 + jp * 8 + 2 * t4 + (q & 1);
                float v = eluf(acc2[mt][jp][q] + sm[CB2S + n]);
                int c3 = n * 8 + p;
                int ch3 = c3 >> 5, hc = c3 & 31;
                int phys = (hc >> 1) ^ xr;
                smh[(CA3W + ch3 * 512 + b * 16 + phys) * 2 + (hc & 1)] = __float2half(v);
            }
        }
    }
    __syncthreads();

    const int wm3 = wid & 1;
    const int wn3 = wid >> 1;
    float acc3[4][4];
#pragma unroll
    for (int jp = 0; jp < 4; jp++)
#pragma unroll
        for (int q = 0; q < 4; q++) acc3[jp][q] = 0.0f;

    for (int i = 0; i < 16; i++) {
        if (i < 14) { CP_WAIT1(); } else { CP_WAIT0(); }
        __syncthreads();
        const uint32_t* Br = smw + CW3R + (i & 1) * 2048;
        const uint32_t* Ab = smw + CA3W + i * 512;
#pragma unroll
        for (int s = 0; s < 2; s++) {
            int w0  = (s * 8 + t4) ^ (2 * g);
            int w1i = (s * 8 + 4 + t4) ^ (2 * g);
            int r0 = wm3 * 16;
            uint32_t a[4];
            a[0] = Ab[(r0 + g) * 16 + w0];
            a[1] = Ab[(r0 + g + 8) * 16 + w0];
            a[2] = Ab[(r0 + g) * 16 + w1i];
            a[3] = Ab[(r0 + g + 8) * 16 + w1i];
#pragma unroll
            for (int jp = 0; jp < 4; jp++) {
                int j8 = wn3 * 4 + jp;
                uint2 bf = *(const uint2*)(Br + (s * 16 + j8) * 64 + lane * 2);
                MMA_F16(acc3[jp], a, bf.x, bf.y);
            }
        }
        __syncthreads();
        if (i + 2 < 16) issueW3(i + 2);
    }

#pragma unroll
    for (int jp = 0; jp < 4; jp++) {
#pragma unroll
        for (int q = 0; q < 4; q++) {
            int r = wm3 * 16 + g + ((q >> 1) << 3);
            int col = wn3 * 32 + jp * 8 + 2 * t4 + (q & 1);
            g_feat[(size_t)(b0g + r) * 128 + col] = eluf(acc3[jp][q] + sm[CB3S + col]);
        }
    }
}

// ---------------- fp16 LSTM-cell GEMM core (R12 half-N CTA, 4-deep ring,
//                  one barrier per TWO K32 chunks) ----------------
// smem words: B ring 4x4096 @0, A ring 4x1024 @16384, bias @20480, hw @20736.
// Total 21888 words = 87552 B (2 CTA/SM). Staging [64][260] reuses B region.
#define AOFF  16384
#define BIASO 20480
#define HWO   20736
#define SMEM_LSTM_WORDS 21888
#define SMEM_LSTM_BYTES (SMEM_LSTM_WORDS * 4)

__device__ __forceinline__ void lstm_core(
    int blk, float* sm, uint32_t smb,
    const float* __restrict__ A0, int lda0, int k0len,
    const float* __restrict__ A1, int k1len,
    const uint32_t* __restrict__ Wp, const float* __restrict__ biasp,
    const float* __restrict__ Cprev, float* __restrict__ Hout, float* __restrict__ Cout,
    const float* __restrict__ h2head, const float* __restrict__ headW,
    const float* __restrict__ headB, float* __restrict__ outPrev)
{
    uint32_t* smw = (uint32_t*)sm;
    float* bias_s = sm + BIASO;
    float* hw_s   = sm + HWO;

    const int tid  = threadIdx.x;
    const int wid  = tid >> 5;
    const int lane = tid & 31;
    const int g    = lane >> 2;
    const int t4   = lane & 3;
    const int wm   = wid & 1;
    const int wn2  = wid >> 1;
    const int half = blk & 1;
    const int row0 = (blk >> 1) * 64;
    const int ar   = tid >> 3;
    const int aq   = tid & 7;

    bias_s[tid] = biasp[half * 256 + tid];
    if (h2head) {
        for (int idx = tid; idx < 1152; idx += 256) {
            int j = idx / 9, o = idx - j * 9;
            hw_s[idx] = headW[o * 128 + j];
        }
    }
    __syncthreads();

    float acc[2][8][4];
#pragma unroll
    for (int mt = 0; mt < 2; mt++)
#pragma unroll
        for (int j8 = 0; j8 < 8; j8++)
#pragma unroll
            for (int q = 0; q < 4; q++) acc[mt][j8][q] = 0.0f;

    const int nch = (k0len + k1len) >> 5;   // always even (4, 8 or 12)
    const int awsw = (2 * aq) ^ (2 * (ar & 7));

    auto ldgA = [&](int i, float4 v[2]) {
        int kb = i << 5;
        const float* src; int ld; int col;
        if (kb < k0len) { src = A0; ld = lda0; col = kb; }
        else            { src = A1; ld = 128;  col = kb - k0len; }
        v[0] = *(const float4*)(src + (size_t)(row0 + ar) * ld + col + aq * 4);
        v[1] = *(const float4*)(src + (size_t)(row0 + ar + 32) * ld + col + aq * 4);
    };
    auto stsA = [&](int i, const float4 v[2]) {
        uint32_t* p = smw + AOFF + (i & 3) * 1024 + ar * 16 + awsw;
        p[0]   = pack_h2(v[0].x, v[0].y);
        p[1]   = pack_h2(v[0].z, v[0].w);
        p[512] = pack_h2(v[1].x, v[1].y);
        p[513] = pack_h2(v[1].z, v[1].w);
    };
    auto issueB = [&](int i) {
        const uint32_t* wsrc = Wp + (size_t)(i * 2 + half) * 4096;
        uint32_t dst = smb + (uint32_t)(i & 3) * 16384u + (uint32_t)tid * 16u;
#pragma unroll
        for (int it = 0; it < 4; it++) {
            CP16(dst + (uint32_t)it * 4096u, wsrc + (size_t)(it * 256 + tid) * 4);
        }
        CP_COMMIT();
    };

    const int xg = 2 * g;
    const int r0a = wm * 32 + g;

    auto compute = [&](int c) {
        const uint32_t* Aw = smw + AOFF + (c & 3) * 1024;
        const uint4*    Bq = (const uint4*)(smw + (c & 3) * 4096) + wn2 * 256;
#pragma unroll
        for (int s = 0; s < 2; s++) {
            uint4 bv[4];
#pragma unroll
            for (int jp = 0; jp < 4; jp++) bv[jp] = Bq[s * 128 + jp * 32 + lane];
            uint32_t a[2][4];
#pragma unroll
            for (int mt = 0; mt < 2; mt++) {
                int r0 = r0a + mt * 16;
                int w0 = (s * 8 + t4) ^ xg;
                int w1 = (s * 8 + 4 + t4) ^ xg;
                a[mt][0] = Aw[r0 * 16 + w0];
                a[mt][1] = Aw[(r0 + 8) * 16 + w0];
                a[mt][2] = Aw[r0 * 16 + w1];
                a[mt][3] = Aw[(r0 + 8) * 16 + w1];
            }
#pragma unroll
            for (int jp = 0; jp < 4; jp++) {
                MMA_F16(acc[0][2 * jp],     a[0], bv[jp].x, bv[jp].y);
                MMA_F16(acc[1][2 * jp],     a[1], bv[jp].x, bv[jp].y);
                MMA_F16(acc[0][2 * jp + 1], a[0], bv[jp].z, bv[jp].w);
                MMA_F16(acc[1][2 * jp + 1], a[1], bv[jp].z, bv[jp].w);
            }
        }
    };

    // ---- prologue: fill chunks 0,1 ----
    {
        float4 v[2];
        ldgA(0, v);
        stsA(0, v);
        ldgA(1, v);
        stsA(1, v);
        issueB(0);
        issueB(1);
    }

    // ---- mainloop: one barrier per two chunks ----
    for (int i = 0; i < nch; i += 2) {
        CP_WAIT0();
        __syncthreads();
        bool p2 = (i + 2 < nch);
        bool p3 = (i + 3 < nch);
        float4 v2[2], v3[2];
        if (p2) { issueB(i + 2); ldgA(i + 2, v2); }
        if (p3) issueB(i + 3);
        compute(i);
        if (p2) stsA(i + 2, v2);
        if (p3) ldgA(i + 3, v3);
        compute(i + 1);
        if (p3) stsA(i + 3, v3);
    }
    __syncthreads();

    // stage gates to [64][260] (R12)
#pragma unroll
    for (int mt = 0; mt < 2; mt++) {
        int row = wm * 32 + mt * 16 + g;
#pragma unroll
        for (int j8 = 0; j8 < 8; j8++) {
            int col = wn2 * 64 + j8 * 8 + 2 * t4;
            sm[row * 260 + col]           = acc[mt][j8][0];
            sm[row * 260 + col + 1]       = acc[mt][j8][1];
            sm[(row + 8) * 260 + col]     = acc[mt][j8][2];
            sm[(row + 8) * 260 + col + 1] = acc[mt][j8][3];
        }
    }
    __syncthreads();

    // cell epilogue (R12)
    {
        const int j0 = tid & 63;
        const int rg = tid >> 6;
        const int col = half * 64 + j0;
        const float4 bb = *(const float4*)(bias_s + 4 * j0);
#pragma unroll
        for (int rr = 0; rr < 16; rr++) {
            int r = rg * 16 + rr;
            int row = row0 + r;
            float4 gv = *(const float4*)(sm + r * 260 + 4 * j0);
            float gi = gv.x + bb.x;
            float gf = gv.y + bb.y;
            float gg = gv.z + bb.z;
            float go = gv.w + bb.w;
            float cp = Cprev ? Cprev[(size_t)row * 128 + col] : 0.0f;
            float c  = sigf(gf) * cp + sigf(gi) * tanhx(gg);
            float h  = sigf(go) * tanhx(c);
            Cout[(size_t)row * 128 + col] = c;
            Hout[(size_t)row * 128 + col] = h;
        }
    }

    // head for an older step's h2 (32 rows per CTA) (R12)
    if (h2head) {
        __syncthreads();
        const int hr0 = row0 + half * 32;
#pragma unroll
        for (int it = 0; it < 4; it++) {
            int idx = tid + it * 256;
            int r = idx >> 5, cq = idx & 31;
            float4 v = *(const float4*)(h2head + (size_t)(hr0 + r) * 128 + cq * 4);
            sm[r * 132 + cq * 4]     = v.x;
            sm[r * 132 + cq * 4 + 1] = v.y;
            sm[r * 132 + cq * 4 + 2] = v.z;
            sm[r * 132 + cq * 4 + 3] = v.w;
        }
        __syncthreads();
        for (int idx = tid; idx < 288; idx += 256) {
            int r = idx / 9, o = idx - r * 9;
            float s = headB[o];
            const float* hr = sm + r * 132;
#pragma unroll 8
            for (int jj = 0; jj < 128; jj++) s += hr[jj] * hw_s[jj * 9 + o];
            outPrev[(size_t)(hr0 + r) * 9 + o] = s;
        }
    }
}

__global__ __launch_bounds__(256, 2)
void lstm_single_kernel(const float* __restrict__ A0, int lda0, int k0len,
                        const float* __restrict__ A1, int k1len,
                        const uint32_t* __restrict__ Wp, const float* __restrict__ biasp,
                        const float* __restrict__ Cprev,
                        float* __restrict__ Hout, float* __restrict__ Cout)
{
    extern __shared__ float sm[];
    uint32_t smb = smem_u32(sm);
    lstm_core(blockIdx.x, sm, smb, A0, lda0, k0len, A1, k1len, Wp, biasp,
              Cprev, Hout, Cout, nullptr, nullptr, nullptr, nullptr);
}

__global__ __launch_bounds__(256, 2)
void lstm_merged_kernel(const float* __restrict__ a0_1, const float* __restrict__ a1_1,
                        const uint32_t* __restrict__ W_1, const float* __restrict__ b_1,
                        const float* __restrict__ cp_1,
                        float* __restrict__ ho_1, float* __restrict__ co_1,
                        const float* __restrict__ h2head, const float* __restrict__ headW,
                        const float* __restrict__ headB, float* __restrict__ outPrev,
                        const float* __restrict__ a0_2, const float* __restrict__ a1_2, int k1_2,
                        const uint32_t* __restrict__ W_2, const float* __restrict__ b_2,
                        const float* __restrict__ cp_2,
                        float* __restrict__ ho_2, float* __restrict__ co_2)
{
    extern __shared__ float sm[];
    uint32_t smb = smem_u32(sm);
    if (blockIdx.x < 1024) {
        lstm_core(blockIdx.x, sm, smb, a0_1, 256, 256, a1_1, 128, W_1, b_1,
                  cp_1, ho_1, co_1, h2head, headW, headB, outPrev);
    } else {
        lstm_core(blockIdx.x - 1024, sm, smb, a0_2, 128, 128, a1_2, k1_2, W_2, b_2,
                  cp_2, ho_2, co_2, nullptr, nullptr, nullptr, nullptr);
    }
}

// ---------------- final head kernel: steps 15 and 16 (exact R12) ----------------
__global__ __launch_bounds__(256)
void head2_kernel(const float* __restrict__ h2a, const float* __restrict__ h2b,
                  const float* __restrict__ headW, const float* __restrict__ headB,
                  float* __restrict__ outA, float* __restrict__ outB)
{
    __shared__ float hs[64 * 132];
    __shared__ float hw[1152];
    const int t = threadIdx.x;
    const bool second = blockIdx.x >= 512;
    const float* h2 = second ? h2b : h2a;
    float* outp = second ? outB : outA;
    const int r0 = (second ? (blockIdx.x - 512) : blockIdx.x) * 64;
    for (int idx = t; idx < 1152; idx += 256) {
        int j = idx / 9, o = idx - j * 9;
        hw[idx] = headW[o * 128 + j];
    }
#pragma unroll
    for (int it = 0; it < 8; it++) {
        int idx = t + it * 256;
        int r = idx >> 5, cq = idx & 31;
        float4 v = *(const float4*)(h2 + (size_t)(r0 + r) * 128 + cq * 4);
        hs[r * 132 + cq * 4]     = v.x;
        hs[r * 132 + cq * 4 + 1] = v.y;
        hs[r * 132 + cq * 4 + 2] = v.z;
        hs[r * 132 + cq * 4 + 3] = v.w;
    }
    __syncthreads();
    for (int idx = t; idx < 576; idx += 256) {
        int r = idx / 9, o = idx - r * 9;
        float s = headB[o];
        const float* hr = hs + r * 132;
#pragma unroll 8
        for (int jj = 0; jj < 128; jj++) s += hr[jj] * hw[jj * 9 + o];
        outp[(size_t)(r0 + r) * 9 + o] = s;
    }
}

// ---------------- launch ----------------
extern "C" void kernel_launch(void* const* d_in, const int* in_sizes, int n_in,
                              void* d_out, int out_size) {
    const float* x        = (const float*)d_in[0];
    const float* ps       = (const float*)d_in[1];
    const float* conv1_w  = (const float*)d_in[2];
    const float* conv1_b  = (const float*)d_in[3];
    const float* conv2_w  = (const float*)d_in[4];
    const float* conv2_b  = (const float*)d_in[5];
    const float* conv3_w  = (const float*)d_in[6];
    const float* conv3_b  = (const float*)d_in[7];
    const float* w_ih1    = (const float*)d_in[8];
    const float* w_hh1    = (const float*)d_in[9];
    const float* b_ih1    = (const float*)d_in[10];
    const float* b_hh1    = (const float*)d_in[11];
    const float* w_ih2    = (const float*)d_in[12];
    const float* w_hh2    = (const float*)d_in[13];
    const float* b_ih2    = (const float*)d_in[14];
    const float* b_hh2    = (const float*)d_in[15];
    const float* head_w   = (const float*)d_in[16];
    const float* head_b   = (const float*)d_in[17];
    float* out = (float*)d_out;

    cudaFuncSetAttribute(conv_kernel, cudaFuncAttributeMaxDynamicSharedMemorySize, CONV_SMEM_BYTES);
    cudaFuncSetAttribute(lstm_single_kernel, cudaFuncAttributeMaxDynamicSharedMemorySize, SMEM_LSTM_BYTES);
    cudaFuncSetAttribute(lstm_merged_kernel, cudaFuncAttributeMaxDynamicSharedMemorySize, SMEM_LSTM_BYTES);

    float *feat, *h1, *h2, *c1, *c2, *b1p, *b2p;
    uint32_t *W1h, *W2h;
    cudaGetSymbolAddress((void**)&feat, g_feat);
    cudaGetSymbolAddress((void**)&h1, g_h1);
    cudaGetSymbolAddress((void**)&h2, g_h2);
    cudaGetSymbolAddress((void**)&c1, g_c1);
    cudaGetSymbolAddress((void**)&c2, g_c2);
    cudaGetSymbolAddress((void**)&W1h, g_W1h);
    cudaGetSymbolAddress((void**)&W2h, g_W2h);
    cudaGetSymbolAddress((void**)&b1p, g_b1p);
    cudaGetSymbolAddress((void**)&b2p, g_b2p);

    const int prep_total = 12 * 8192 + 8 * 8192 + 1024 + 7168 + 32768;
    prep_kernel<<<(prep_total + 255) / 256, 256>>>(w_ih1, w_hh1, b_ih1, b_hh1,
                                                   w_ih2, w_hh2, b_ih2, b_hh2,
                                                   conv2_w, conv3_w);

    conv_kernel<<<Bn / 32, 256, CONV_SMEM_BYTES>>>(x, conv1_w, conv1_b, conv2_b, conv3_b);

    // L1_0: writes h1[0], c1
    lstm_single_kernel<<<1024, 256, SMEM_LSTM_BYTES>>>(
        feat, 128, 128, nullptr, 0, W1h, b1p, nullptr, h1, c1);

    // merged steps: launch s = [L1_s | L2_{s-1}]
    for (int s = 1; s <= Tn; s++) {
        const float* A      = ps + (size_t)(s - 1) * Bn * 256;
        const float* h1prev = h1 + (size_t)((s - 1) & 1) * BH;
        float*       h1out  = h1 + (size_t)(s & 1) * BH;
        const float* h2old  = h2 + (size_t)(s & 1) * BH;        // h2_{s-2}, valid s>=2
        float*       h2out  = h2 + (size_t)((s - 1) & 1) * BH;  // h2_{s-1}
        lstm_merged_kernel<<<2048, 256, SMEM_LSTM_BYTES>>>(
            A, h1prev, W1h, b1p, c1, h1out, c1,
            (s >= 2) ? h2old : nullptr, head_w, head_b,
            (s >= 2) ? (out + (size_t)(s - 2) * Bn * 9) : nullptr,
            h1prev, (s >= 2) ? h2old : nullptr, (s >= 2) ? 128 : 0,
            W2h, b2p, (s >= 2) ? c2 : nullptr, h2out, c2);
    }

    // L2_16: h1_16 = h1[0], h2_15 = h2[1] -> h2[0]
    lstm_single_kernel<<<1024, 256, SMEM_LSTM_BYTES>>>(
        h1, 128, 128, h2 + BH, 128, W2h, b2p, c2, h2, c2);

    // heads for steps 15 and 16
    head2_kernel<<<1024, 256>>>(h2 + BH, h2, head_w, head_b,
                                out + (size_t)15 * Bn * 9, out + (size_t)16 * Bn * 9);
}